// round 1
// baseline (speedup 1.0000x reference)
#include <cuda_runtime.h>
#include <math.h>

#define R_TOT 16384
#define S_LEN 4096
#define D_DIM 128
#define K_LNK 13
#define M_NET 12

// Scratch (no allocations allowed) ------------------------------------------
__device__ float g_X[R_TOT * D_DIM];                 // token+pos embeddings
__device__ float g_Vres[R_TOT * D_DIM];              // V0 = residual
__device__ float g_Vb0[R_TOT * D_DIM];               // scan ping
__device__ float g_Vb1[R_TOT * D_DIM];               // scan pong
__device__ float g_Wall[M_NET * R_TOT * K_LNK];      // per-step mixing weights

__device__ __forceinline__ float gelu_exact(float x) {
    return 0.5f * x * (1.0f + erff(x * 0.70710678118654752440f));
}

// ---------------------------------------------------------------------------
// Kernel 1: x = emb[data] + apc  (float4 per thread)
// ---------------------------------------------------------------------------
__global__ void k_embed(const int* __restrict__ data,
                        const float* __restrict__ emb,
                        const float* __restrict__ apc) {
    int idx = blockIdx.x * blockDim.x + threadIdx.x;   // float4 index
    int row = idx >> 5;
    int c4  = idx & 31;
    int tok = data[row];
    int s   = row & (S_LEN - 1);
    float4 e = ((const float4*)emb)[tok * 32 + c4];
    float4 a = ((const float4*)apc)[s * 32 + c4];
    e.x += a.x; e.y += a.y; e.z += a.z; e.w += a.w;
    ((float4*)g_X)[idx] = e;
}

// ---------------------------------------------------------------------------
// Kernel 2: fused 2-layer MLP.  grid = (256 row-tiles, 13 nets)
//   m == 0 : V0 = gelu(X@gW1+gb1)@gW2+gb2          -> g_Vres
//   m >= 1 : W_all[m-1] = gelu(X@fW1+fb1)@fW2+fb2  -> g_Wall
// ---------------------------------------------------------------------------
#define XS_STRIDE 132                    // 64x128 tile, padded (bank-safe)
#define SM_WS   0
#define SM_XS   16384
#define SM_W2S  (16384 + 8448)
#define SM_B1   (SM_W2S + 1664)
#define SM_B2   (SM_B1 + 128)
#define SMEM_FLOATS (SM_B2 + 128)
#define SMEM_BYTES  (SMEM_FLOATS * 4)    // 107008 B

__device__ __forceinline__ void fma_tile(float acc[4][8],
                                         float x0, float x1, float x2, float x3,
                                         float4 wA, float4 wB) {
    acc[0][0] += x0*wA.x; acc[0][1] += x0*wA.y; acc[0][2] += x0*wA.z; acc[0][3] += x0*wA.w;
    acc[0][4] += x0*wB.x; acc[0][5] += x0*wB.y; acc[0][6] += x0*wB.z; acc[0][7] += x0*wB.w;
    acc[1][0] += x1*wA.x; acc[1][1] += x1*wA.y; acc[1][2] += x1*wA.z; acc[1][3] += x1*wA.w;
    acc[1][4] += x1*wB.x; acc[1][5] += x1*wB.y; acc[1][6] += x1*wB.z; acc[1][7] += x1*wB.w;
    acc[2][0] += x2*wA.x; acc[2][1] += x2*wA.y; acc[2][2] += x2*wA.z; acc[2][3] += x2*wA.w;
    acc[2][4] += x2*wB.x; acc[2][5] += x2*wB.y; acc[2][6] += x2*wB.z; acc[2][7] += x2*wB.w;
    acc[3][0] += x3*wA.x; acc[3][1] += x3*wA.y; acc[3][2] += x3*wA.z; acc[3][3] += x3*wA.w;
    acc[3][4] += x3*wB.x; acc[3][5] += x3*wB.y; acc[3][6] += x3*wB.z; acc[3][7] += x3*wB.w;
}

// 64x128 tile GEMM: acc[4][8] for thread (tc, tr4); inputs in smem.
__device__ __forceinline__ void tile_mm(const float* __restrict__ Ws,
                                        const float* __restrict__ Hs,
                                        int tc, int tr4, float acc[4][8]) {
    #pragma unroll
    for (int i = 0; i < 4; ++i)
        #pragma unroll
        for (int j = 0; j < 8; ++j) acc[i][j] = 0.0f;
    const float* wp = Ws + tc * 8;
    #pragma unroll 4
    for (int d = 0; d < 128; ++d) {
        float4 wA = *(const float4*)(wp + d * 128);
        float4 wB = *(const float4*)(wp + d * 128 + 4);
        float x0 = Hs[(tr4 + 0) * XS_STRIDE + d];
        float x1 = Hs[(tr4 + 1) * XS_STRIDE + d];
        float x2 = Hs[(tr4 + 2) * XS_STRIDE + d];
        float x3 = Hs[(tr4 + 3) * XS_STRIDE + d];
        fma_tile(acc, x0, x1, x2, x3, wA, wB);
    }
}

extern __shared__ float smem[];

__global__ __launch_bounds__(256, 2) void k_mlp(
    const float* __restrict__ gW1, const float* __restrict__ gb1,
    const float* __restrict__ gW2, const float* __restrict__ gb2,
    const float* __restrict__ fW1, const float* __restrict__ fb1,
    const float* __restrict__ fW2, const float* __restrict__ fb2) {
    float* Ws  = smem + SM_WS;     // 128x128 W1 (then W2 for m==0)
    float* Xs  = smem + SM_XS;     // 64x132 X tile (reused as H)
    float* W2s = smem + SM_W2S;    // 128x13 (f nets)
    float* b1s = smem + SM_B1;
    float* b2s = smem + SM_B2;

    const int tid  = threadIdx.x;
    const int m    = blockIdx.y;
    const int row0 = blockIdx.x * 64;

    const float* W1 = (m == 0) ? gW1 : fW1 + (size_t)(m - 1) * 128 * 128;
    const float* b1 = (m == 0) ? gb1 : fb1 + (m - 1) * 128;

    // Stage W1 (64 KB) and X tile (33 KB) into smem
    #pragma unroll
    for (int p = 0; p < 16; ++p)
        ((float4*)Ws)[tid + p * 256] = ((const float4*)W1)[tid + p * 256];
    const float* Xg = g_X + (size_t)row0 * 128;
    #pragma unroll
    for (int p = 0; p < 8; ++p) {
        int q = tid + p * 256;
        int r = q >> 5, c4 = q & 31;
        ((float4*)(Xs + r * XS_STRIDE))[c4] = ((const float4*)(Xg + r * 128))[c4];
    }
    if (tid < 128) b1s[tid] = b1[tid];
    if (m > 0) {
        const float* W2 = fW2 + (size_t)(m - 1) * 128 * 13;
        for (int p = tid; p < 128 * 13; p += 256) W2s[p] = W2[p];
        if (tid < 13) b2s[tid] = fb2[(m - 1) * 13 + tid];
    }
    __syncthreads();

    const int tc  = tid & 15;
    const int tr4 = (tid >> 4) * 4;

    // ---- Layer 1: H = gelu(X @ W1 + b1) ----
    float acc[4][8];
    tile_mm(Ws, Xs, tc, tr4, acc);
    __syncthreads();                       // all reads of Xs done

    #pragma unroll
    for (int i = 0; i < 4; ++i)
        #pragma unroll
        for (int j = 0; j < 8; ++j)
            Xs[(tr4 + i) * XS_STRIDE + tc * 8 + j] =
                gelu_exact(acc[i][j] + b1s[tc * 8 + j]);

    if (m == 0) {                          // stage gW2 into Ws for phase 2
        #pragma unroll
        for (int p = 0; p < 16; ++p)
            ((float4*)Ws)[tid + p * 256] = ((const float4*)gW2)[tid + p * 256];
        if (tid < 128) b2s[tid] = gb2[tid];
    }
    __syncthreads();

    // ---- Layer 2 ----
    if (m == 0) {
        float acc2[4][8];
        tile_mm(Ws, Xs, tc, tr4, acc2);
        #pragma unroll
        for (int i = 0; i < 4; ++i) {
            float* op = g_Vres + (size_t)(row0 + tr4 + i) * 128 + tc * 8;
            float4 oA, oB;
            oA.x = acc2[i][0] + b2s[tc * 8 + 0];
            oA.y = acc2[i][1] + b2s[tc * 8 + 1];
            oA.z = acc2[i][2] + b2s[tc * 8 + 2];
            oA.w = acc2[i][3] + b2s[tc * 8 + 3];
            oB.x = acc2[i][4] + b2s[tc * 8 + 4];
            oB.y = acc2[i][5] + b2s[tc * 8 + 5];
            oB.z = acc2[i][6] + b2s[tc * 8 + 6];
            oB.w = acc2[i][7] + b2s[tc * 8 + 7];
            *(float4*)op       = oA;
            *(float4*)(op + 4) = oB;
        }
    } else {
        const int c   = tid & 15;
        const int rr4 = (tid >> 4) * 4;
        if (c < 13) {
            float s0 = 0.f, s1 = 0.f, s2 = 0.f, s3 = 0.f;
            #pragma unroll 4
            for (int d = 0; d < 128; ++d) {
                float w = W2s[d * 13 + c];
                s0 += Xs[(rr4 + 0) * XS_STRIDE + d] * w;
                s1 += Xs[(rr4 + 1) * XS_STRIDE + d] * w;
                s2 += Xs[(rr4 + 2) * XS_STRIDE + d] * w;
                s3 += Xs[(rr4 + 3) * XS_STRIDE + d] * w;
            }
            float bb = b2s[c];
            float* op = g_Wall + (size_t)(m - 1) * R_TOT * K_LNK
                               + (size_t)row0 * K_LNK;
            op[(rr4 + 0) * K_LNK + c] = s0 + bb;
            op[(rr4 + 1) * K_LNK + c] = s1 + bb;
            op[(rr4 + 2) * K_LNK + c] = s2 + bb;
            op[(rr4 + 3) * K_LNK + c] = s3 + bb;
        }
    }
}

// ---------------------------------------------------------------------------
// Kernel 3: one chord-mix scan step.
//   Vout[b,i,:] = sum_k W[b,i,k] * Vin[b, cols[i,k], :] + Vres[b,i,:]
// 256 threads = 2 rows of 128 lanes.
// ---------------------------------------------------------------------------
__global__ void k_scan(int m, const int* __restrict__ cols,
                       float* __restrict__ out_final) {
    const float* Vin  = (m == 0) ? g_Vres : (((m - 1) & 1) == 0 ? g_Vb0 : g_Vb1);
    float*       Vout = (m == M_NET - 1) ? out_final
                                         : ((m & 1) == 0 ? g_Vb0 : g_Vb1);
    const float* Wm = g_Wall + (size_t)m * R_TOT * K_LNK;

    __shared__ float ws[2][K_LNK];
    __shared__ int   ci[2][K_LNK];

    const int rloc = threadIdx.x >> 7;      // 0 / 1
    const int d    = threadIdx.x & 127;
    const int row  = blockIdx.x * 2 + rloc;
    const int s    = row & (S_LEN - 1);
    const int b    = row >> 12;

    if (d < K_LNK) {
        ws[rloc][d] = Wm[row * K_LNK + d];
        ci[rloc][d] = ((b << 12) + cols[s * K_LNK + d]) << 7;   // *128
    }
    __syncthreads();

    float acc = g_Vres[(row << 7) + d];
    #pragma unroll
    for (int k = 0; k < K_LNK; ++k)
        acc += ws[rloc][k] * Vin[ci[rloc][k] + d];
    Vout[(row << 7) + d] = acc;
}

// ---------------------------------------------------------------------------
extern "C" void kernel_launch(void* const* d_in, const int* in_sizes, int n_in,
                              void* d_out, int out_size) {
    const int*   data = (const int*)  d_in[0];
    const int*   cols = (const int*)  d_in[1];
    const float* emb  = (const float*)d_in[2];
    const float* apc  = (const float*)d_in[3];
    const float* gW1  = (const float*)d_in[4];
    const float* gb1  = (const float*)d_in[5];
    const float* gW2  = (const float*)d_in[6];
    const float* gb2  = (const float*)d_in[7];
    const float* fW1  = (const float*)d_in[8];
    const float* fb1  = (const float*)d_in[9];
    const float* fW2  = (const float*)d_in[10];
    const float* fb2  = (const float*)d_in[11];
    float* out = (float*)d_out;

    cudaFuncSetAttribute(k_mlp, cudaFuncAttributeMaxDynamicSharedMemorySize,
                         SMEM_BYTES);

    // 1) embeddings
    k_embed<<<(R_TOT * 32) / 256, 256>>>(data, emb, apc);

    // 2) all 13 fused MLPs (g net + 12 f nets)
    dim3 grid_mlp(R_TOT / 64, 13);
    k_mlp<<<grid_mlp, 256, SMEM_BYTES>>>(gW1, gb1, gW2, gb2,
                                         fW1, fb1, fW2, fb2);

    // 3) 12 chord-mix scan steps (ping-pong, last writes d_out)
    for (int m = 0; m < M_NET; ++m)
        k_scan<<<R_TOT / 2, 256>>>(m, cols, out);
}

// round 2
// speedup vs baseline: 1.1910x; 1.1910x over previous
#include <cuda_runtime.h>
#include <math.h>

#define R_TOT 16384
#define S_LEN 4096
#define D_DIM 128
#define K_LNK 13
#define M_NET 12

typedef unsigned long long u64;

// Scratch (no allocations allowed) ------------------------------------------
__device__ float g_X[R_TOT * D_DIM];                 // token+pos embeddings
__device__ float g_Vres[R_TOT * D_DIM];              // V0 = residual
__device__ float g_Vb0[R_TOT * D_DIM];               // scan ping
__device__ float g_Vb1[R_TOT * D_DIM];               // scan pong
__device__ float g_Wall[M_NET * R_TOT * K_LNK];      // per-step mixing weights

__device__ __forceinline__ float gelu_exact(float x) {
    return 0.5f * x * (1.0f + erff(x * 0.70710678118654752440f));
}

// ---- packed f32x2 helpers (fma.rn.f32x2: 2x fp32 throughput, same rounding) ----
__device__ __forceinline__ u64 bcast2(float x) {
    u64 r; unsigned xu = __float_as_uint(x);
    asm("mov.b64 %0, {%1, %1};" : "=l"(r) : "r"(xu));
    return r;
}
__device__ __forceinline__ void unpack2(u64 v, float& lo, float& hi) {
    unsigned a, b;
    asm("mov.b64 {%0, %1}, %2;" : "=r"(a), "=r"(b) : "l"(v));
    lo = __uint_as_float(a); hi = __uint_as_float(b);
}
__device__ __forceinline__ void ffma2(u64& d, u64 a, u64 b) {
    asm("fma.rn.f32x2 %0, %1, %2, %0;" : "+l"(d) : "l"(a), "l"(b));
}

// ---------------------------------------------------------------------------
// Kernel 1: x = emb[data] + apc  (float4 per thread)
// ---------------------------------------------------------------------------
__global__ void k_embed(const int* __restrict__ data,
                        const float* __restrict__ emb,
                        const float* __restrict__ apc) {
    int idx = blockIdx.x * blockDim.x + threadIdx.x;   // float4 index
    int row = idx >> 5;
    int c4  = idx & 31;
    int tok = data[row];
    int s   = row & (S_LEN - 1);
    float4 e = ((const float4*)emb)[tok * 32 + c4];
    float4 a = ((const float4*)apc)[s * 32 + c4];
    e.x += a.x; e.y += a.y; e.z += a.z; e.w += a.w;
    ((float4*)g_X)[idx] = e;
}

// ---------------------------------------------------------------------------
// Kernel 2: fused 2-layer MLP.  grid = (256 row-tiles, 13 nets)
//   m == 0 : V0 = gelu(X@gW1+gb1)@gW2+gb2          -> g_Vres
//   m >= 1 : W_all[m-1] = gelu(X@fW1+fb1)@fW2+fb2  -> g_Wall
// ---------------------------------------------------------------------------
#define XS_STRIDE 132                    // 64x128 tile, padded (bank-safe)
#define SM_WS   0
#define SM_XS   16384
#define SM_W2S  (16384 + 8448)
#define SM_B1   (SM_W2S + 1664)
#define SM_B2   (SM_B1 + 128)
#define SMEM_FLOATS (SM_B2 + 128)
#define SMEM_BYTES  (SMEM_FLOATS * 4)    // 107008 B

// 64x128 tile GEMM with packed f32x2 accumulators.
// acc[i][jp] holds output columns (tc*8 + 2*jp, tc*8 + 2*jp + 1) for row tr4+i.
__device__ __forceinline__ void tile_mm2(const float* __restrict__ Ws,
                                         const float* __restrict__ Hs,
                                         int tc, int tr4, u64 acc[4][4]) {
    #pragma unroll
    for (int i = 0; i < 4; ++i)
        #pragma unroll
        for (int j = 0; j < 4; ++j) acc[i][j] = 0ULL;
    const float* wp = Ws + tc * 8;
    #pragma unroll 4
    for (int d = 0; d < 128; ++d) {
        ulonglong2 wa = *(const ulonglong2*)(wp + d * 128);      // cols 0..3
        ulonglong2 wb = *(const ulonglong2*)(wp + d * 128 + 4);  // cols 4..7
        u64 x0 = bcast2(Hs[(tr4 + 0) * XS_STRIDE + d]);
        u64 x1 = bcast2(Hs[(tr4 + 1) * XS_STRIDE + d]);
        u64 x2 = bcast2(Hs[(tr4 + 2) * XS_STRIDE + d]);
        u64 x3 = bcast2(Hs[(tr4 + 3) * XS_STRIDE + d]);
        ffma2(acc[0][0], x0, wa.x); ffma2(acc[0][1], x0, wa.y);
        ffma2(acc[0][2], x0, wb.x); ffma2(acc[0][3], x0, wb.y);
        ffma2(acc[1][0], x1, wa.x); ffma2(acc[1][1], x1, wa.y);
        ffma2(acc[1][2], x1, wb.x); ffma2(acc[1][3], x1, wb.y);
        ffma2(acc[2][0], x2, wa.x); ffma2(acc[2][1], x2, wa.y);
        ffma2(acc[2][2], x2, wb.x); ffma2(acc[2][3], x2, wb.y);
        ffma2(acc[3][0], x3, wa.x); ffma2(acc[3][1], x3, wa.y);
        ffma2(acc[3][2], x3, wb.x); ffma2(acc[3][3], x3, wb.y);
    }
}

extern __shared__ float smem[];

__global__ __launch_bounds__(256, 2) void k_mlp(
    const float* __restrict__ gW1, const float* __restrict__ gb1,
    const float* __restrict__ gW2, const float* __restrict__ gb2,
    const float* __restrict__ fW1, const float* __restrict__ fb1,
    const float* __restrict__ fW2, const float* __restrict__ fb2) {
    float* Ws  = smem + SM_WS;     // 128x128 W1 (then W2 for m==0)
    float* Xs  = smem + SM_XS;     // 64x132 X tile (reused as H)
    float* W2s = smem + SM_W2S;    // 128x13 (f nets)
    float* b1s = smem + SM_B1;
    float* b2s = smem + SM_B2;

    const int tid  = threadIdx.x;
    const int m    = blockIdx.y;
    const int row0 = blockIdx.x * 64;

    const float* W1 = (m == 0) ? gW1 : fW1 + (size_t)(m - 1) * 128 * 128;
    const float* b1 = (m == 0) ? gb1 : fb1 + (m - 1) * 128;

    // Stage W1 (64 KB) and X tile (33 KB) into smem
    #pragma unroll
    for (int p = 0; p < 16; ++p)
        ((float4*)Ws)[tid + p * 256] = ((const float4*)W1)[tid + p * 256];
    const float* Xg = g_X + (size_t)row0 * 128;
    #pragma unroll
    for (int p = 0; p < 8; ++p) {
        int q = tid + p * 256;
        int r = q >> 5, c4 = q & 31;
        ((float4*)(Xs + r * XS_STRIDE))[c4] = ((const float4*)(Xg + r * 128))[c4];
    }
    if (tid < 128) b1s[tid] = b1[tid];
    if (m > 0) {
        const float* W2 = fW2 + (size_t)(m - 1) * 128 * 13;
        for (int p = tid; p < 128 * 13; p += 256) W2s[p] = W2[p];
        if (tid < 13) b2s[tid] = fb2[(m - 1) * 13 + tid];
    }
    __syncthreads();

    const int tc  = tid & 15;
    const int tr4 = (tid >> 4) * 4;

    // ---- Layer 1: H = gelu(X @ W1 + b1) ----
    u64 acc[4][4];
    tile_mm2(Ws, Xs, tc, tr4, acc);
    __syncthreads();                       // all reads of Xs done

    #pragma unroll
    for (int i = 0; i < 4; ++i)
        #pragma unroll
        for (int jp = 0; jp < 4; ++jp) {
            float lo, hi; unpack2(acc[i][jp], lo, hi);
            int j = jp * 2;
            Xs[(tr4 + i) * XS_STRIDE + tc * 8 + j] =
                gelu_exact(lo + b1s[tc * 8 + j]);
            Xs[(tr4 + i) * XS_STRIDE + tc * 8 + j + 1] =
                gelu_exact(hi + b1s[tc * 8 + j + 1]);
        }

    if (m == 0) {                          // stage gW2 into Ws for phase 2
        #pragma unroll
        for (int p = 0; p < 16; ++p)
            ((float4*)Ws)[tid + p * 256] = ((const float4*)gW2)[tid + p * 256];
        if (tid < 128) b2s[tid] = gb2[tid];
    }
    __syncthreads();

    // ---- Layer 2 ----
    if (m == 0) {
        u64 acc2[4][4];
        tile_mm2(Ws, Xs, tc, tr4, acc2);
        #pragma unroll
        for (int i = 0; i < 4; ++i) {
            float o[8];
            #pragma unroll
            for (int jp = 0; jp < 4; ++jp) {
                float lo, hi; unpack2(acc2[i][jp], lo, hi);
                o[jp * 2]     = lo + b2s[tc * 8 + jp * 2];
                o[jp * 2 + 1] = hi + b2s[tc * 8 + jp * 2 + 1];
            }
            float* op = g_Vres + (size_t)(row0 + tr4 + i) * 128 + tc * 8;
            *(float4*)op       = make_float4(o[0], o[1], o[2], o[3]);
            *(float4*)(op + 4) = make_float4(o[4], o[5], o[6], o[7]);
        }
    } else {
        const int c   = tid & 15;
        const int rr4 = (tid >> 4) * 4;
        if (c < 13) {
            float s0 = 0.f, s1 = 0.f, s2 = 0.f, s3 = 0.f;
            #pragma unroll 4
            for (int d = 0; d < 128; ++d) {
                float w = W2s[d * 13 + c];
                s0 += Xs[(rr4 + 0) * XS_STRIDE + d] * w;
                s1 += Xs[(rr4 + 1) * XS_STRIDE + d] * w;
                s2 += Xs[(rr4 + 2) * XS_STRIDE + d] * w;
                s3 += Xs[(rr4 + 3) * XS_STRIDE + d] * w;
            }
            float bb = b2s[c];
            float* op = g_Wall + (size_t)(m - 1) * R_TOT * K_LNK
                               + (size_t)row0 * K_LNK;
            op[(rr4 + 0) * K_LNK + c] = s0 + bb;
            op[(rr4 + 1) * K_LNK + c] = s1 + bb;
            op[(rr4 + 2) * K_LNK + c] = s2 + bb;
            op[(rr4 + 3) * K_LNK + c] = s3 + bb;
        }
    }
}

// ---------------------------------------------------------------------------
// Kernel 3: one chord-mix scan step.
//   Vout[b,i,:] = sum_k W[b,i,k] * Vin[b, cols[i,k], :] + Vres[b,i,:]
// One warp per row; float4 per lane; (w, col) broadcast via shfl (no smem,
// no block sync).
// ---------------------------------------------------------------------------
__global__ void __launch_bounds__(256) k_scan(int m, const int* __restrict__ cols,
                                              float* __restrict__ out_final) {
    const float* Vin  = (m == 0) ? g_Vres : (((m - 1) & 1) ? g_Vb1 : g_Vb0);
    float*       Vout = (m == M_NET - 1) ? out_final
                                         : ((m & 1) ? g_Vb1 : g_Vb0);
    const float* Wm = g_Wall + (size_t)m * R_TOT * K_LNK;

    const int lane = threadIdx.x & 31;
    const int row  = (blockIdx.x * blockDim.x + threadIdx.x) >> 5;
    const int s    = row & (S_LEN - 1);
    const int b    = row >> 12;

    float wv = 0.0f; int iv = 0;
    if (lane < K_LNK) {
        wv = Wm[row * K_LNK + lane];
        iv = ((b << 12) | cols[s * K_LNK + lane]) << 5;   // row base in float4s
    }

    const float4* Vin4 = (const float4*)Vin;
    float4 acc = ((const float4*)g_Vres)[(row << 5) + lane];
    #pragma unroll
    for (int k = 0; k < K_LNK; ++k) {
        float wk = __shfl_sync(0xffffffffu, wv, k);
        int   ik = __shfl_sync(0xffffffffu, iv, k);
        float4 v = Vin4[ik + lane];
        acc.x += wk * v.x; acc.y += wk * v.y;
        acc.z += wk * v.z; acc.w += wk * v.w;
    }
    ((float4*)Vout)[(row << 5) + lane] = acc;
}

// ---------------------------------------------------------------------------
extern "C" void kernel_launch(void* const* d_in, const int* in_sizes, int n_in,
                              void* d_out, int out_size) {
    const int*   data = (const int*)  d_in[0];
    const int*   cols = (const int*)  d_in[1];
    const float* emb  = (const float*)d_in[2];
    const float* apc  = (const float*)d_in[3];
    const float* gW1  = (const float*)d_in[4];
    const float* gb1  = (const float*)d_in[5];
    const float* gW2  = (const float*)d_in[6];
    const float* gb2  = (const float*)d_in[7];
    const float* fW1  = (const float*)d_in[8];
    const float* fb1  = (const float*)d_in[9];
    const float* fW2  = (const float*)d_in[10];
    const float* fb2  = (const float*)d_in[11];
    float* out = (float*)d_out;

    cudaFuncSetAttribute(k_mlp, cudaFuncAttributeMaxDynamicSharedMemorySize,
                         SMEM_BYTES);

    // 1) embeddings
    k_embed<<<(R_TOT * 32) / 256, 256>>>(data, emb, apc);

    // 2) all 13 fused MLPs (g net + 12 f nets)
    dim3 grid_mlp(R_TOT / 64, 13);
    k_mlp<<<grid_mlp, 256, SMEM_BYTES>>>(gW1, gb1, gW2, gb2,
                                         fW1, fb1, fW2, fb2);

    // 3) 12 chord-mix scan steps (ping-pong, last writes d_out)
    for (int m = 0; m < M_NET; ++m)
        k_scan<<<R_TOT / 8, 256>>>(m, cols, out);
}

// round 5
// speedup vs baseline: 2.2206x; 1.8644x over previous
#include <cuda_runtime.h>
#include <cuda_bf16.h>
#include <math.h>
#include <stdint.h>

#define R_TOT 16384
#define S_LEN 4096
#define D_DIM 128
#define K_LNK 13
#define M_NET 12

typedef unsigned int u32;
typedef unsigned long long u64;

// ---------------- scratch (static device memory only) ----------------------
__device__ __nv_bfloat16 g_Xhi[R_TOT * D_DIM];          // X hi, row-major
__device__ __nv_bfloat16 g_Xlo[R_TOT * D_DIM];          // X lo
__device__ __nv_bfloat16 g_B1hi[13 * 128 * 128];        // W1^T [net][n][k]
__device__ __nv_bfloat16 g_B1lo[13 * 128 * 128];
__device__ __nv_bfloat16 g_B2ghi[128 * 128];            // gW2^T [n][k]
__device__ __nv_bfloat16 g_B2glo[128 * 128];
__device__ __nv_bfloat16 g_B2fhi[12 * 16 * 128];        // fW2^T padded N=16
__device__ __nv_bfloat16 g_B2flo[12 * 16 * 128];
__device__ float g_Vres[R_TOT * D_DIM];
__device__ float g_Vb0[R_TOT * D_DIM];
__device__ float g_Vb1[R_TOT * D_DIM];
__device__ float g_Wall[M_NET * R_TOT * K_LNK];

// ---------------- helpers ---------------------------------------------------
__device__ __forceinline__ u32 smem_u32(const void* p) {
    u32 a;
    asm("{ .reg .u64 t; cvta.to.shared.u64 t, %1; cvt.u32.u64 %0, t; }"
        : "=r"(a) : "l"(p));
    return a;
}
__device__ __forceinline__ void ldsm4(u32* r, u32 addr) {
    asm volatile("ldmatrix.sync.aligned.m8n8.x4.shared.b16 {%0,%1,%2,%3}, [%4];"
        : "=r"(r[0]), "=r"(r[1]), "=r"(r[2]), "=r"(r[3]) : "r"(addr));
}
__device__ __forceinline__ void mma16816(float* d, const u32* a, const u32* b) {
    asm volatile(
        "mma.sync.aligned.m16n8k16.row.col.f32.bf16.bf16.f32 "
        "{%0,%1,%2,%3}, {%4,%5,%6,%7}, {%8,%9}, {%0,%1,%2,%3};"
        : "+f"(d[0]), "+f"(d[1]), "+f"(d[2]), "+f"(d[3])
        : "r"(a[0]), "r"(a[1]), "r"(a[2]), "r"(a[3]), "r"(b[0]), "r"(b[1]));
}
// swizzled byte address of 16B unit (r, c16) in a [rows][128]bf16 smem tile
__device__ __forceinline__ u32 sw_addr(u32 base, int r, int c16) {
    return base + (u32)(((r << 4) + (c16 ^ (r & 7))) << 4);
}
__device__ __forceinline__ void bf_split(float v, unsigned short& h,
                                         unsigned short& l) {
    __nv_bfloat16 hb = __float2bfloat16(v);
    __nv_bfloat16 lb = __float2bfloat16(v - __bfloat162float(hb));
    h = __bfloat16_as_ushort(hb);
    l = __bfloat16_as_ushort(lb);
}
__device__ __forceinline__ float gelu_exact(float x) {
    return 0.5f * x * (1.0f + erff(x * 0.70710678118654752440f));
}

// ---------------------------------------------------------------------------
// Prep: transpose + bf16-split weights into [n][k] row-major hi/lo.
// ---------------------------------------------------------------------------
#define PREP_A (13 * 128 * 64)
#define PREP_B (128 * 64)
#define PREP_C (12 * 16 * 64)
#define PREP_TOT (PREP_A + PREP_B + PREP_C)

__global__ void k_prep(const float* __restrict__ gW1,
                       const float* __restrict__ gW2,
                       const float* __restrict__ fW1,
                       const float* __restrict__ fW2) {
    int t = blockIdx.x * blockDim.x + threadIdx.x;
    if (t >= PREP_TOT) return;

    float w0, w1;
    u32* dh;
    u32* dl;
    int widx;
    if (t < PREP_A) {
        int net = t >> 13;                 // /8192
        int r = t & 8191;
        int n = r >> 6, k = (r & 63) * 2;
        const float* W1 = (net == 0) ? gW1 : fW1 + (size_t)(net - 1) * 128 * 128;
        w0 = W1[k * 128 + n];
        w1 = W1[(k + 1) * 128 + n];
        widx = (net * 128 + n) * 64 + (k >> 1);
        dh = (u32*)g_B1hi; dl = (u32*)g_B1lo;
    } else if (t < PREP_A + PREP_B) {
        int r = t - PREP_A;
        int n = r >> 6, k = (r & 63) * 2;
        w0 = gW2[k * 128 + n];
        w1 = gW2[(k + 1) * 128 + n];
        widx = n * 64 + (k >> 1);
        dh = (u32*)g_B2ghi; dl = (u32*)g_B2glo;
    } else {
        int r = t - PREP_A - PREP_B;
        int net = r >> 10;                 // /1024
        int rr = r & 1023;
        int n = rr >> 6, k = (rr & 63) * 2;
        w0 = (n < 13) ? fW2[(size_t)net * 128 * 13 + k * 13 + n] : 0.0f;
        w1 = (n < 13) ? fW2[(size_t)net * 128 * 13 + (k + 1) * 13 + n] : 0.0f;
        widx = (net * 16 + n) * 64 + (k >> 1);
        dh = (u32*)g_B2fhi; dl = (u32*)g_B2flo;
    }
    unsigned short h0, l0, h1, l1;
    bf_split(w0, h0, l0);
    bf_split(w1, h1, l1);
    dh[widx] = (u32)h0 | ((u32)h1 << 16);
    dl[widx] = (u32)l0 | ((u32)l1 << 16);
}

// ---------------------------------------------------------------------------
// Embed: x = emb[data] + apc -> bf16 hi/lo row-major.
// ---------------------------------------------------------------------------
__global__ void k_embed(const int* __restrict__ data,
                        const float* __restrict__ emb,
                        const float* __restrict__ apc) {
    int idx = blockIdx.x * blockDim.x + threadIdx.x;   // R_TOT*16 threads
    int row = idx >> 4;
    int g8 = idx & 15;
    int tok = data[row];
    int s = row & (S_LEN - 1);
    float4 e0 = ((const float4*)emb)[tok * 32 + g8 * 2];
    float4 e1 = ((const float4*)emb)[tok * 32 + g8 * 2 + 1];
    float4 a0 = ((const float4*)apc)[s * 32 + g8 * 2];
    float4 a1 = ((const float4*)apc)[s * 32 + g8 * 2 + 1];
    float v[8] = {e0.x + a0.x, e0.y + a0.y, e0.z + a0.z, e0.w + a0.w,
                  e1.x + a1.x, e1.y + a1.y, e1.z + a1.z, e1.w + a1.w};
    u32 hp[4], lp[4];
    #pragma unroll
    for (int p = 0; p < 4; ++p) {
        unsigned short h0, l0, h1, l1;
        bf_split(v[2 * p], h0, l0);
        bf_split(v[2 * p + 1], h1, l1);
        hp[p] = (u32)h0 | ((u32)h1 << 16);
        lp[p] = (u32)l0 | ((u32)l1 << 16);
    }
    ((uint4*)g_Xhi)[row * 16 + g8] = make_uint4(hp[0], hp[1], hp[2], hp[3]);
    ((uint4*)g_Xlo)[row * 16 + g8] = make_uint4(lp[0], lp[1], lp[2], lp[3]);
}

// ---------------------------------------------------------------------------
// k_mlp: warp-MMA (mma.sync bf16 hi/lo split) fused 2-layer MLP.
// grid = (128 row-tiles, 13 nets), 256 threads.
// smem: W1hi/lo (gW2 for layer2 of m==0), XH hi/lo (X then H), W2f hi/lo.
// ---------------------------------------------------------------------------
#define SM_W1HI  0
#define SM_W1LO  32768
#define SM_XHHI  65536
#define SM_XHLO  98304
#define SM_F2HI  131072
#define SM_F2LO  135168
#define SM_B1S   139264
#define SM_B2S   139776
#define SMEM_MLP 140288

extern __shared__ char smc[];

__global__ void __launch_bounds__(256, 1) k_mlp(
    const float* __restrict__ gb1, const float* __restrict__ gb2,
    const float* __restrict__ fb1, const float* __restrict__ fb2) {
    const int tid = threadIdx.x;
    const int lane = tid & 31;
    const int wid = tid >> 5;
    const int m = blockIdx.y;
    const int row0 = blockIdx.x * 128;
    const u32 sbase = smem_u32(smc);
    float* b1s = (float*)(smc + SM_B1S);
    float* b2s = (float*)(smc + SM_B2S);

    // ---- stage W1^T hi/lo and X hi/lo into swizzled smem ----
    {
        const uint4* s1h = (const uint4*)g_B1hi + m * 2048;
        const uint4* s1l = (const uint4*)g_B1lo + m * 2048;
        const uint4* sxh = (const uint4*)g_Xhi + row0 * 16;
        const uint4* sxl = (const uint4*)g_Xlo + row0 * 16;
        #pragma unroll
        for (int p = 0; p < 8; ++p) {
            int q = tid + p * 256;
            int r = q >> 4, c16 = q & 15;
            u32 d = (u32)(((r << 4) + (c16 ^ (r & 7))) << 4);
            *(uint4*)(smc + SM_W1HI + d) = s1h[q];
            *(uint4*)(smc + SM_W1LO + d) = s1l[q];
            *(uint4*)(smc + SM_XHHI + d) = sxh[q];
            *(uint4*)(smc + SM_XHLO + d) = sxl[q];
        }
    }
    if (m > 0) {
        const uint4* sfh = (const uint4*)g_B2fhi + (m - 1) * 256;
        const uint4* sfl = (const uint4*)g_B2flo + (m - 1) * 256;
        if (tid < 256) {
            int r = tid >> 4, c16 = tid & 15;
            u32 d = (u32)(((r << 4) + (c16 ^ (r & 7))) << 4);
            *(uint4*)(smc + SM_F2HI + d) = sfh[tid];
            *(uint4*)(smc + SM_F2LO + d) = sfl[tid];
        }
        if (tid < 128) b1s[tid] = fb1[(m - 1) * 128 + tid];
        if (tid < 16)  b2s[tid] = (tid < 13) ? fb2[(m - 1) * 13 + tid] : 0.0f;
    } else {
        if (tid < 128) { b1s[tid] = gb1[tid]; b2s[tid] = gb2[tid]; }
    }
    __syncthreads();

    // fragment lane offsets
    const int a_ro = (lane & 7) + (lane & 8);
    const int a_co = lane >> 4;
    const int b_ro = (lane & 7) + ((lane >> 1) & 8);
    const int b_co = (lane >> 3) & 1;
    const int tq = lane >> 2;
    const int tr = (lane & 3) * 2;

    const int wm = (wid & 3) * 32;    // warp M offset (layer1 / layer2-g)
    const int wn = (wid >> 2) * 64;   // warp N offset

    // ================= Layer 1: H = gelu(X @ W1 + b1) ======================
    float acc[2][8][4];
    #pragma unroll
    for (int i = 0; i < 2; ++i)
        #pragma unroll
        for (int j = 0; j < 8; ++j)
            #pragma unroll
            for (int q = 0; q < 4; ++q) acc[i][j][q] = 0.0f;

    #pragma unroll
    for (int k = 0; k < 8; ++k) {
        const int kc = k * 2;
        u32 ah[2][4], al[2][4], bh[4][4], bl[4][4];
        #pragma unroll
        for (int mt = 0; mt < 2; ++mt) {
            int r = wm + mt * 16 + a_ro;
            ldsm4(ah[mt], sw_addr(sbase + SM_XHHI, r, kc + a_co));
            ldsm4(al[mt], sw_addr(sbase + SM_XHLO, r, kc + a_co));
        }
        #pragma unroll
        for (int ng = 0; ng < 4; ++ng) {
            int r = wn + ng * 16 + b_ro;
            ldsm4(bh[ng], sw_addr(sbase + SM_W1HI, r, kc + b_co));
            ldsm4(bl[ng], sw_addr(sbase + SM_W1LO, r, kc + b_co));
        }
        #pragma unroll
        for (int mt = 0; mt < 2; ++mt)
            #pragma unroll
            for (int ng = 0; ng < 4; ++ng) {
                mma16816(acc[mt][2 * ng],     ah[mt], &bh[ng][0]);
                mma16816(acc[mt][2 * ng + 1], ah[mt], &bh[ng][2]);
                mma16816(acc[mt][2 * ng],     ah[mt], &bl[ng][0]);
                mma16816(acc[mt][2 * ng + 1], ah[mt], &bl[ng][2]);
                mma16816(acc[mt][2 * ng],     al[mt], &bh[ng][0]);
                mma16816(acc[mt][2 * ng + 1], al[mt], &bh[ng][2]);
            }
    }
    __syncthreads();   // everyone done reading X before H overwrites it

    // epilogue 1: bias + gelu + bf16 split, H -> XH region
    #pragma unroll
    for (int mt = 0; mt < 2; ++mt)
        #pragma unroll
        for (int nt = 0; nt < 8; ++nt) {
            int r = wm + mt * 16 + tq;
            int c = wn + nt * 8 + tr;
            float v0 = gelu_exact(acc[mt][nt][0] + b1s[c]);
            float v1 = gelu_exact(acc[mt][nt][1] + b1s[c + 1]);
            float v2 = gelu_exact(acc[mt][nt][2] + b1s[c]);
            float v3 = gelu_exact(acc[mt][nt][3] + b1s[c + 1]);
            unsigned short h0, l0, h1, l1, h2, l2, h3, l3;
            bf_split(v0, h0, l0); bf_split(v1, h1, l1);
            bf_split(v2, h2, l2); bf_split(v3, h3, l3);
            int c16 = c >> 3, cb = (c & 7) * 2;
            u32 d0 = sw_addr(sbase + SM_XHHI, r, c16) - sbase + cb;
            u32 d8 = sw_addr(sbase + SM_XHHI, r + 8, c16) - sbase + cb;
            *(u32*)(smc + d0) = (u32)h0 | ((u32)h1 << 16);
            *(u32*)(smc + d8) = (u32)h2 | ((u32)h3 << 16);
            d0 += (SM_XHLO - SM_XHHI); d8 += (SM_XHLO - SM_XHHI);
            *(u32*)(smc + d0) = (u32)l0 | ((u32)l1 << 16);
            *(u32*)(smc + d8) = (u32)l2 | ((u32)l3 << 16);
        }

    // m==0: restage gW2^T over the consumed W1 region
    if (m == 0) {
        const uint4* s2h = (const uint4*)g_B2ghi;
        const uint4* s2l = (const uint4*)g_B2glo;
        #pragma unroll
        for (int p = 0; p < 8; ++p) {
            int q = tid + p * 256;
            int r = q >> 4, c16 = q & 15;
            u32 d = (u32)(((r << 4) + (c16 ^ (r & 7))) << 4);
            *(uint4*)(smc + SM_W1HI + d) = s2h[q];
            *(uint4*)(smc + SM_W1LO + d) = s2l[q];
        }
    }
    __syncthreads();

    // ================= Layer 2 =============================================
    if (m == 0) {
        float ac2[2][8][4];
        #pragma unroll
        for (int i = 0; i < 2; ++i)
            #pragma unroll
            for (int j = 0; j < 8; ++j)
                #pragma unroll
                for (int q = 0; q < 4; ++q) ac2[i][j][q] = 0.0f;
        #pragma unroll
        for (int k = 0; k < 8; ++k) {
            const int kc = k * 2;
            u32 ah[2][4], al[2][4], bh[4][4], bl[4][4];
            #pragma unroll
            for (int mt = 0; mt < 2; ++mt) {
                int r = wm + mt * 16 + a_ro;
                ldsm4(ah[mt], sw_addr(sbase + SM_XHHI, r, kc + a_co));
                ldsm4(al[mt], sw_addr(sbase + SM_XHLO, r, kc + a_co));
            }
            #pragma unroll
            for (int ng = 0; ng < 4; ++ng) {
                int r = wn + ng * 16 + b_ro;
                ldsm4(bh[ng], sw_addr(sbase + SM_W1HI, r, kc + b_co));
                ldsm4(bl[ng], sw_addr(sbase + SM_W1LO, r, kc + b_co));
            }
            #pragma unroll
            for (int mt = 0; mt < 2; ++mt)
                #pragma unroll
                for (int ng = 0; ng < 4; ++ng) {
                    mma16816(ac2[mt][2 * ng],     ah[mt], &bh[ng][0]);
                    mma16816(ac2[mt][2 * ng + 1], ah[mt], &bh[ng][2]);
                    mma16816(ac2[mt][2 * ng],     ah[mt], &bl[ng][0]);
                    mma16816(ac2[mt][2 * ng + 1], ah[mt], &bl[ng][2]);
                    mma16816(ac2[mt][2 * ng],     al[mt], &bh[ng][0]);
                    mma16816(ac2[mt][2 * ng + 1], al[mt], &bh[ng][2]);
                }
        }
        #pragma unroll
        for (int mt = 0; mt < 2; ++mt)
            #pragma unroll
            for (int nt = 0; nt < 8; ++nt) {
                int r = wm + mt * 16 + tq;
                int c = wn + nt * 8 + tr;
                float2 o0 = make_float2(ac2[mt][nt][0] + b2s[c],
                                        ac2[mt][nt][1] + b2s[c + 1]);
                float2 o1 = make_float2(ac2[mt][nt][2] + b2s[c],
                                        ac2[mt][nt][3] + b2s[c + 1]);
                *(float2*)(g_Vres + (size_t)(row0 + r) * 128 + c) = o0;
                *(float2*)(g_Vres + (size_t)(row0 + r + 8) * 128 + c) = o1;
            }
    } else {
        const int wm2 = wid * 16;
        float ac2[2][4];
        #pragma unroll
        for (int j = 0; j < 2; ++j)
            #pragma unroll
            for (int q = 0; q < 4; ++q) ac2[j][q] = 0.0f;
        #pragma unroll
        for (int k = 0; k < 8; ++k) {
            const int kc = k * 2;
            u32 ah[4], al[4], bh[4], bl[4];
            int r = wm2 + a_ro;
            ldsm4(ah, sw_addr(sbase + SM_XHHI, r, kc + a_co));
            ldsm4(al, sw_addr(sbase + SM_XHLO, r, kc + a_co));
            ldsm4(bh, sw_addr(sbase + SM_F2HI, b_ro, kc + b_co));
            ldsm4(bl, sw_addr(sbase + SM_F2LO, b_ro, kc + b_co));
            mma16816(ac2[0], ah, &bh[0]);
            mma16816(ac2[1], ah, &bh[2]);
            mma16816(ac2[0], ah, &bl[0]);
            mma16816(ac2[1], ah, &bl[2]);
            mma16816(ac2[0], al, &bh[0]);
            mma16816(ac2[1], al, &bh[2]);
        }
        float* op = g_Wall + (size_t)(m - 1) * R_TOT * K_LNK
                           + (size_t)row0 * K_LNK;
        #pragma unroll
        for (int nt = 0; nt < 2; ++nt) {
            int c = nt * 8 + tr;
            int r = wm2 + tq;
            if (c < 13) {
                op[(r) * K_LNK + c]     = ac2[nt][0] + b2s[c];
                op[(r + 8) * K_LNK + c] = ac2[nt][2] + b2s[c];
            }
            if (c + 1 < 13) {
                op[(r) * K_LNK + c + 1]     = ac2[nt][1] + b2s[c + 1];
                op[(r + 8) * K_LNK + c + 1] = ac2[nt][3] + b2s[c + 1];
            }
        }
    }
}

// ---------------------------------------------------------------------------
// k_scan: one chord-mix step. One warp per TWO rows, float4/lane,
// (w, idx) broadcast via shfl: lanes 0-12 hold row A's, 16-28 row B's.
// ---------------------------------------------------------------------------
__global__ void __launch_bounds__(256) k_scan(int m, const int* __restrict__ cols,
                                              float* __restrict__ out_final) {
    const float* Vin  = (m == 0) ? g_Vres : (((m - 1) & 1) ? g_Vb1 : g_Vb0);
    float*       Vout = (m == M_NET - 1) ? out_final
                                         : ((m & 1) ? g_Vb1 : g_Vb0);
    const float* Wm = g_Wall + (size_t)m * R_TOT * K_LNK;

    const int lane = threadIdx.x & 31;
    const int pair = (blockIdx.x * blockDim.x + threadIdx.x) >> 5;
    const int r0 = pair * 2;
    const int r1 = r0 + 1;

    const int lr = (lane >= 16) ? r1 : r0;
    const int lk = lane & 15;
    float wv = 0.0f; int iv = 0;
    if (lk < K_LNK) {
        int s = lr & (S_LEN - 1);
        int b = lr >> 12;
        wv = Wm[lr * K_LNK + lk];
        iv = ((b << 12) | cols[s * K_LNK + lk]) << 5;
    }

    const float4* Vin4 = (const float4*)Vin;
    float4 a0 = ((const float4*)g_Vres)[(r0 << 5) + lane];
    float4 a1 = ((const float4*)g_Vres)[(r1 << 5) + lane];
    #pragma unroll
    for (int k = 0; k < K_LNK; ++k) {
        float w0 = __shfl_sync(0xffffffffu, wv, k);
        int   i0 = __shfl_sync(0xffffffffu, iv, k);
        float w1 = __shfl_sync(0xffffffffu, wv, k + 16);
        int   i1 = __shfl_sync(0xffffffffu, iv, k + 16);
        float4 v0 = Vin4[i0 + lane];
        float4 v1 = Vin4[i1 + lane];
        a0.x += w0 * v0.x; a0.y += w0 * v0.y;
        a0.z += w0 * v0.z; a0.w += w0 * v0.w;
        a1.x += w1 * v1.x; a1.y += w1 * v1.y;
        a1.z += w1 * v1.z; a1.w += w1 * v1.w;
    }
    ((float4*)Vout)[(r0 << 5) + lane] = a0;
    ((float4*)Vout)[(r1 << 5) + lane] = a1;
}

// ---------------------------------------------------------------------------
extern "C" void kernel_launch(void* const* d_in, const int* in_sizes, int n_in,
                              void* d_out, int out_size) {
    const int*   data = (const int*)  d_in[0];
    const int*   cols = (const int*)  d_in[1];
    const float* emb  = (const float*)d_in[2];
    const float* apc  = (const float*)d_in[3];
    const float* gW1  = (const float*)d_in[4];
    const float* gb1  = (const float*)d_in[5];
    const float* gW2  = (const float*)d_in[6];
    const float* gb2  = (const float*)d_in[7];
    const float* fW1  = (const float*)d_in[8];
    const float* fb1  = (const float*)d_in[9];
    const float* fW2  = (const float*)d_in[10];
    const float* fb2  = (const float*)d_in[11];
    float* out = (float*)d_out;

    cudaFuncSetAttribute(k_mlp, cudaFuncAttributeMaxDynamicSharedMemorySize,
                         SMEM_MLP);

    // 1) weight prep (transpose + bf16 split)
    k_prep<<<(PREP_TOT + 255) / 256, 256>>>(gW1, gW2, fW1, fW2);

    // 2) embeddings -> bf16 hi/lo
    k_embed<<<(R_TOT * 16) / 256, 256>>>(data, emb, apc);

    // 3) all 13 fused MLPs on warp tensor cores
    dim3 grid_mlp(R_TOT / 128, 13);
    k_mlp<<<grid_mlp, 256, SMEM_MLP>>>(gb1, gb2, fb1, fb2);

    // 4) 12 chord-mix scan steps
    for (int m = 0; m < M_NET; ++m)
        k_scan<<<R_TOT / 16, 256>>>(m, cols, out);
}

// round 8
// speedup vs baseline: 2.3619x; 1.0636x over previous
#include <cuda_runtime.h>
#include <cuda_bf16.h>
#include <math.h>
#include <stdint.h>

#define R_TOT 16384
#define S_LEN 4096
#define D_DIM 128
#define K_LNK 13
#define M_NET 12

typedef unsigned int u32;
typedef unsigned long long u64;

// ---------------- scratch (static device memory only) ----------------------
__device__ __nv_bfloat16 g_Xhi[R_TOT * D_DIM];          // X hi, row-major
__device__ __nv_bfloat16 g_Xlo[R_TOT * D_DIM];          // X lo
__device__ __nv_bfloat16 g_B1hi[13 * 128 * 128];        // W1^T [net][n][k]
__device__ __nv_bfloat16 g_B1lo[13 * 128 * 128];
__device__ __nv_bfloat16 g_B2ghi[128 * 128];            // gW2^T [n][k]
__device__ __nv_bfloat16 g_B2glo[128 * 128];
__device__ __nv_bfloat16 g_B2fhi[12 * 16 * 128];        // fW2^T padded N=16
__device__ __nv_bfloat16 g_B2flo[12 * 16 * 128];
__device__ float g_Vres[R_TOT * D_DIM];
__device__ float g_Vb0[R_TOT * D_DIM];
__device__ float g_Vb1[R_TOT * D_DIM];
__device__ float g_Wall[M_NET * R_TOT * K_LNK];

// ---------------- helpers ---------------------------------------------------
__device__ __forceinline__ u32 smem_u32(const void* p) {
    u32 a;
    asm("{ .reg .u64 t; cvta.to.shared.u64 t, %1; cvt.u32.u64 %0, t; }"
        : "=r"(a) : "l"(p));
    return a;
}
__device__ __forceinline__ void ldsm4(u32* r, u32 addr) {
    asm volatile("ldmatrix.sync.aligned.m8n8.x4.shared.b16 {%0,%1,%2,%3}, [%4];"
        : "=r"(r[0]), "=r"(r[1]), "=r"(r[2]), "=r"(r[3]) : "r"(addr));
}
__device__ __forceinline__ void mma16816(float* d, const u32* a, const u32* b) {
    asm volatile(
        "mma.sync.aligned.m16n8k16.row.col.f32.bf16.bf16.f32 "
        "{%0,%1,%2,%3}, {%4,%5,%6,%7}, {%8,%9}, {%0,%1,%2,%3};"
        : "+f"(d[0]), "+f"(d[1]), "+f"(d[2]), "+f"(d[3])
        : "r"(a[0]), "r"(a[1]), "r"(a[2]), "r"(a[3]), "r"(b[0]), "r"(b[1]));
}
// swizzled byte address of 16B unit (r, c16) in a [rows][128]bf16 smem tile
__device__ __forceinline__ u32 sw_addr(u32 base, int r, int c16) {
    return base + (u32)(((r << 4) + (c16 ^ (r & 7))) << 4);
}
__device__ __forceinline__ void bf_split(float v, unsigned short& h,
                                         unsigned short& l) {
    __nv_bfloat16 hb = __float2bfloat16(v);
    __nv_bfloat16 lb = __float2bfloat16(v - __bfloat162float(hb));
    h = __bfloat16_as_ushort(hb);
    l = __bfloat16_as_ushort(lb);
}
__device__ __forceinline__ float gelu_exact(float x) {
    return 0.5f * x * (1.0f + erff(x * 0.70710678118654752440f));
}

// ---------------------------------------------------------------------------
// Prep: transpose + bf16-split weights into [n][k] row-major hi/lo.
// ---------------------------------------------------------------------------
#define PREP_A (13 * 128 * 64)
#define PREP_B (128 * 64)
#define PREP_C (12 * 16 * 64)
#define PREP_TOT (PREP_A + PREP_B + PREP_C)

__global__ void k_prep(const float* __restrict__ gW1,
                       const float* __restrict__ gW2,
                       const float* __restrict__ fW1,
                       const float* __restrict__ fW2) {
    int t = blockIdx.x * blockDim.x + threadIdx.x;
    if (t >= PREP_TOT) return;

    float w0, w1;
    u32* dh;
    u32* dl;
    int widx;
    if (t < PREP_A) {
        int net = t >> 13;                 // /8192
        int r = t & 8191;
        int n = r >> 6, k = (r & 63) * 2;
        const float* W1 = (net == 0) ? gW1 : fW1 + (size_t)(net - 1) * 128 * 128;
        w0 = W1[k * 128 + n];
        w1 = W1[(k + 1) * 128 + n];
        widx = (net * 128 + n) * 64 + (k >> 1);
        dh = (u32*)g_B1hi; dl = (u32*)g_B1lo;
    } else if (t < PREP_A + PREP_B) {
        int r = t - PREP_A;
        int n = r >> 6, k = (r & 63) * 2;
        w0 = gW2[k * 128 + n];
        w1 = gW2[(k + 1) * 128 + n];
        widx = n * 64 + (k >> 1);
        dh = (u32*)g_B2ghi; dl = (u32*)g_B2glo;
    } else {
        int r = t - PREP_A - PREP_B;
        int net = r >> 10;                 // /1024
        int rr = r & 1023;
        int n = rr >> 6, k = (rr & 63) * 2;
        w0 = (n < 13) ? fW2[(size_t)net * 128 * 13 + k * 13 + n] : 0.0f;
        w1 = (n < 13) ? fW2[(size_t)net * 128 * 13 + (k + 1) * 13 + n] : 0.0f;
        widx = (net * 16 + n) * 64 + (k >> 1);
        dh = (u32*)g_B2fhi; dl = (u32*)g_B2flo;
    }
    unsigned short h0, l0, h1, l1;
    bf_split(w0, h0, l0);
    bf_split(w1, h1, l1);
    dh[widx] = (u32)h0 | ((u32)h1 << 16);
    dl[widx] = (u32)l0 | ((u32)l1 << 16);
}

// ---------------------------------------------------------------------------
// Embed: x = emb[data] + apc -> bf16 hi/lo row-major.
// ---------------------------------------------------------------------------
__global__ void k_embed(const int* __restrict__ data,
                        const float* __restrict__ emb,
                        const float* __restrict__ apc) {
    int idx = blockIdx.x * blockDim.x + threadIdx.x;   // R_TOT*16 threads
    int row = idx >> 4;
    int g8 = idx & 15;
    int tok = data[row];
    int s = row & (S_LEN - 1);
    float4 e0 = ((const float4*)emb)[tok * 32 + g8 * 2];
    float4 e1 = ((const float4*)emb)[tok * 32 + g8 * 2 + 1];
    float4 a0 = ((const float4*)apc)[s * 32 + g8 * 2];
    float4 a1 = ((const float4*)apc)[s * 32 + g8 * 2 + 1];
    float v[8] = {e0.x + a0.x, e0.y + a0.y, e0.z + a0.z, e0.w + a0.w,
                  e1.x + a1.x, e1.y + a1.y, e1.z + a1.z, e1.w + a1.w};
    u32 hp[4], lp[4];
    #pragma unroll
    for (int p = 0; p < 4; ++p) {
        unsigned short h0, l0, h1, l1;
        bf_split(v[2 * p], h0, l0);
        bf_split(v[2 * p + 1], h1, l1);
        hp[p] = (u32)h0 | ((u32)h1 << 16);
        lp[p] = (u32)l0 | ((u32)l1 << 16);
    }
    ((uint4*)g_Xhi)[row * 16 + g8] = make_uint4(hp[0], hp[1], hp[2], hp[3]);
    ((uint4*)g_Xlo)[row * 16 + g8] = make_uint4(lp[0], lp[1], lp[2], lp[3]);
}

// ---------------------------------------------------------------------------
// k_mlp: warp-MMA (mma.sync bf16 hi/lo split) fused 2-layer MLP.
// grid = (128 row-tiles, 13 nets), 512 threads (16 warps, warp tile 32x32).
// ---------------------------------------------------------------------------
#define SM_W1HI  0
#define SM_W1LO  32768
#define SM_XHHI  65536
#define SM_XHLO  98304
#define SM_F2HI  131072
#define SM_F2LO  135168
#define SM_B1S   139264
#define SM_B2S   139776
#define SMEM_MLP 140288

extern __shared__ char smc[];

__global__ void __launch_bounds__(512, 1) k_mlp(
    const float* __restrict__ gb1, const float* __restrict__ gb2,
    const float* __restrict__ fb1, const float* __restrict__ fb2) {
    const int tid = threadIdx.x;
    const int lane = tid & 31;
    const int wid = tid >> 5;
    const int m = blockIdx.y;
    const int row0 = blockIdx.x * 128;
    const u32 sbase = smem_u32(smc);
    float* b1s = (float*)(smc + SM_B1S);
    float* b2s = (float*)(smc + SM_B2S);

    // ---- stage W1^T hi/lo and X hi/lo into swizzled smem ----
    {
        const uint4* s1h = (const uint4*)g_B1hi + m * 2048;
        const uint4* s1l = (const uint4*)g_B1lo + m * 2048;
        const uint4* sxh = (const uint4*)g_Xhi + row0 * 16;
        const uint4* sxl = (const uint4*)g_Xlo + row0 * 16;
        #pragma unroll
        for (int p = 0; p < 4; ++p) {
            int q = tid + p * 512;
            int r = q >> 4, c16 = q & 15;
            u32 d = (u32)(((r << 4) + (c16 ^ (r & 7))) << 4);
            *(uint4*)(smc + SM_W1HI + d) = s1h[q];
            *(uint4*)(smc + SM_W1LO + d) = s1l[q];
            *(uint4*)(smc + SM_XHHI + d) = sxh[q];
            *(uint4*)(smc + SM_XHLO + d) = sxl[q];
        }
    }
    if (m > 0) {
        const uint4* sfh = (const uint4*)g_B2fhi + (m - 1) * 256;
        const uint4* sfl = (const uint4*)g_B2flo + (m - 1) * 256;
        if (tid < 256) {
            int r = tid >> 4, c16 = tid & 15;
            u32 d = (u32)(((r << 4) + (c16 ^ (r & 7))) << 4);
            *(uint4*)(smc + SM_F2HI + d) = sfh[tid];
            *(uint4*)(smc + SM_F2LO + d) = sfl[tid];
        }
        if (tid < 128) b1s[tid] = fb1[(m - 1) * 128 + tid];
        if (tid < 16)  b2s[tid] = (tid < 13) ? fb2[(m - 1) * 13 + tid] : 0.0f;
    } else {
        if (tid < 128) { b1s[tid] = gb1[tid]; b2s[tid] = gb2[tid]; }
    }
    __syncthreads();

    // fragment lane offsets
    const int a_ro = (lane & 7) + (lane & 8);
    const int a_co = lane >> 4;
    const int b_ro = (lane & 7) + ((lane >> 1) & 8);
    const int b_co = (lane >> 3) & 1;
    const int tq = lane >> 2;
    const int tr = (lane & 3) * 2;

    const int wm = (wid & 3) * 32;    // warp M offset
    const int wn = (wid >> 2) * 32;   // warp N offset

    // ================= Layer 1: H = gelu(X @ W1 + b1) ======================
    float acc[2][4][4];
    #pragma unroll
    for (int i = 0; i < 2; ++i)
        #pragma unroll
        for (int j = 0; j < 4; ++j)
            #pragma unroll
            for (int q = 0; q < 4; ++q) acc[i][j][q] = 0.0f;

    #pragma unroll
    for (int k = 0; k < 8; ++k) {
        const int kc = k * 2;
        u32 ah[2][4], al[2][4], bh[2][4], bl[2][4];
        #pragma unroll
        for (int mt = 0; mt < 2; ++mt) {
            int r = wm + mt * 16 + a_ro;
            ldsm4(ah[mt], sw_addr(sbase + SM_XHHI, r, kc + a_co));
            ldsm4(al[mt], sw_addr(sbase + SM_XHLO, r, kc + a_co));
        }
        #pragma unroll
        for (int ng = 0; ng < 2; ++ng) {
            int r = wn + ng * 16 + b_ro;
            ldsm4(bh[ng], sw_addr(sbase + SM_W1HI, r, kc + b_co));
            ldsm4(bl[ng], sw_addr(sbase + SM_W1LO, r, kc + b_co));
        }
        #pragma unroll
        for (int mt = 0; mt < 2; ++mt)
            #pragma unroll
            for (int ng = 0; ng < 2; ++ng) {
                mma16816(acc[mt][2 * ng],     ah[mt], &bh[ng][0]);
                mma16816(acc[mt][2 * ng + 1], ah[mt], &bh[ng][2]);
                mma16816(acc[mt][2 * ng],     ah[mt], &bl[ng][0]);
                mma16816(acc[mt][2 * ng + 1], ah[mt], &bl[ng][2]);
                mma16816(acc[mt][2 * ng],     al[mt], &bh[ng][0]);
                mma16816(acc[mt][2 * ng + 1], al[mt], &bh[ng][2]);
            }
    }
    __syncthreads();   // everyone done reading X before H overwrites it

    // epilogue 1: bias + gelu + bf16 split, H -> XH region
    #pragma unroll
    for (int mt = 0; mt < 2; ++mt)
        #pragma unroll
        for (int nt = 0; nt < 4; ++nt) {
            int r = wm + mt * 16 + tq;
            int c = wn + nt * 8 + tr;
            float v0 = gelu_exact(acc[mt][nt][0] + b1s[c]);
            float v1 = gelu_exact(acc[mt][nt][1] + b1s[c + 1]);
            float v2 = gelu_exact(acc[mt][nt][2] + b1s[c]);
            float v3 = gelu_exact(acc[mt][nt][3] + b1s[c + 1]);
            unsigned short h0, l0, h1, l1, h2, l2, h3, l3;
            bf_split(v0, h0, l0); bf_split(v1, h1, l1);
            bf_split(v2, h2, l2); bf_split(v3, h3, l3);
            int c16 = c >> 3, cb = (c & 7) * 2;
            u32 d0 = sw_addr(sbase + SM_XHHI, r, c16) - sbase + cb;
            u32 d8 = sw_addr(sbase + SM_XHHI, r + 8, c16) - sbase + cb;
            *(u32*)(smc + d0) = (u32)h0 | ((u32)h1 << 16);
            *(u32*)(smc + d8) = (u32)h2 | ((u32)h3 << 16);
            d0 += (SM_XHLO - SM_XHHI); d8 += (SM_XHLO - SM_XHHI);
            *(u32*)(smc + d0) = (u32)l0 | ((u32)l1 << 16);
            *(u32*)(smc + d8) = (u32)l2 | ((u32)l3 << 16);
        }

    // m==0: restage gW2^T over the consumed W1 region
    if (m == 0) {
        const uint4* s2h = (const uint4*)g_B2ghi;
        const uint4* s2l = (const uint4*)g_B2glo;
        #pragma unroll
        for (int p = 0; p < 4; ++p) {
            int q = tid + p * 512;
            int r = q >> 4, c16 = q & 15;
            u32 d = (u32)(((r << 4) + (c16 ^ (r & 7))) << 4);
            *(uint4*)(smc + SM_W1HI + d) = s2h[q];
            *(uint4*)(smc + SM_W1LO + d) = s2l[q];
        }
    }
    __syncthreads();

    // ================= Layer 2 =============================================
    if (m == 0) {
        float ac2[2][4][4];
        #pragma unroll
        for (int i = 0; i < 2; ++i)
            #pragma unroll
            for (int j = 0; j < 4; ++j)
                #pragma unroll
                for (int q = 0; q < 4; ++q) ac2[i][j][q] = 0.0f;
        #pragma unroll
        for (int k = 0; k < 8; ++k) {
            const int kc = k * 2;
            u32 ah[2][4], al[2][4], bh[2][4], bl[2][4];
            #pragma unroll
            for (int mt = 0; mt < 2; ++mt) {
                int r = wm + mt * 16 + a_ro;
                ldsm4(ah[mt], sw_addr(sbase + SM_XHHI, r, kc + a_co));
                ldsm4(al[mt], sw_addr(sbase + SM_XHLO, r, kc + a_co));
            }
            #pragma unroll
            for (int ng = 0; ng < 2; ++ng) {
                int r = wn + ng * 16 + b_ro;
                ldsm4(bh[ng], sw_addr(sbase + SM_W1HI, r, kc + b_co));
                ldsm4(bl[ng], sw_addr(sbase + SM_W1LO, r, kc + b_co));
            }
            #pragma unroll
            for (int mt = 0; mt < 2; ++mt)
                #pragma unroll
                for (int ng = 0; ng < 2; ++ng) {
                    mma16816(ac2[mt][2 * ng],     ah[mt], &bh[ng][0]);
                    mma16816(ac2[mt][2 * ng + 1], ah[mt], &bh[ng][2]);
                    mma16816(ac2[mt][2 * ng],     ah[mt], &bl[ng][0]);
                    mma16816(ac2[mt][2 * ng + 1], ah[mt], &bl[ng][2]);
                    mma16816(ac2[mt][2 * ng],     al[mt], &bh[ng][0]);
                    mma16816(ac2[mt][2 * ng + 1], al[mt], &bh[ng][2]);
                }
        }
        #pragma unroll
        for (int mt = 0; mt < 2; ++mt)
            #pragma unroll
            for (int nt = 0; nt < 4; ++nt) {
                int r = wm + mt * 16 + tq;
                int c = wn + nt * 8 + tr;
                float2 o0 = make_float2(ac2[mt][nt][0] + b2s[c],
                                        ac2[mt][nt][1] + b2s[c + 1]);
                float2 o1 = make_float2(ac2[mt][nt][2] + b2s[c],
                                        ac2[mt][nt][3] + b2s[c + 1]);
                *(float2*)(g_Vres + (size_t)(row0 + r) * 128 + c) = o0;
                *(float2*)(g_Vres + (size_t)(row0 + r + 8) * 128 + c) = o1;
            }
    } else if (wid < 8) {
        const int wm2 = wid * 16;
        float ac2[2][4];
        #pragma unroll
        for (int j = 0; j < 2; ++j)
            #pragma unroll
            for (int q = 0; q < 4; ++q) ac2[j][q] = 0.0f;
        #pragma unroll
        for (int k = 0; k < 8; ++k) {
            const int kc = k * 2;
            u32 ah[4], al[4], bh[4], bl[4];
            int r = wm2 + a_ro;
            ldsm4(ah, sw_addr(sbase + SM_XHHI, r, kc + a_co));
            ldsm4(al, sw_addr(sbase + SM_XHLO, r, kc + a_co));
            ldsm4(bh, sw_addr(sbase + SM_F2HI, b_ro, kc + b_co));
            ldsm4(bl, sw_addr(sbase + SM_F2LO, b_ro, kc + b_co));
            mma16816(ac2[0], ah, &bh[0]);
            mma16816(ac2[1], ah, &bh[2]);
            mma16816(ac2[0], ah, &bl[0]);
            mma16816(ac2[1], ah, &bl[2]);
            mma16816(ac2[0], al, &bh[0]);
            mma16816(ac2[1], al, &bh[2]);
        }
        float* op = g_Wall + (size_t)(m - 1) * R_TOT * K_LNK
                           + (size_t)row0 * K_LNK;
        #pragma unroll
        for (int nt = 0; nt < 2; ++nt) {
            int c = nt * 8 + tr;
            int r = wm2 + tq;
            if (c < 13) {
                op[(r) * K_LNK + c]     = ac2[nt][0] + b2s[c];
                op[(r + 8) * K_LNK + c] = ac2[nt][2] + b2s[c];
            }
            if (c + 1 < 13) {
                op[(r) * K_LNK + c + 1]     = ac2[nt][1] + b2s[c + 1];
                op[(r + 8) * K_LNK + c + 1] = ac2[nt][3] + b2s[c + 1];
            }
        }
    }
}

// ---------------------------------------------------------------------------
// k_scan: one chord-mix step. One warp per row, float4/lane, shfl broadcast.
// ---------------------------------------------------------------------------
__global__ void __launch_bounds__(256) k_scan(int m, const int* __restrict__ cols,
                                              float* __restrict__ out_final) {
    const float* Vin  = (m == 0) ? g_Vres : (((m - 1) & 1) ? g_Vb1 : g_Vb0);
    float*       Vout = (m == M_NET - 1) ? out_final
                                         : ((m & 1) ? g_Vb1 : g_Vb0);
    const float* Wm = g_Wall + (size_t)m * R_TOT * K_LNK;

    const int lane = threadIdx.x & 31;
    const int row  = (blockIdx.x * blockDim.x + threadIdx.x) >> 5;
    const int s    = row & (S_LEN - 1);
    const int b    = row >> 12;

    float wv = 0.0f; int iv = 0;
    if (lane < K_LNK) {
        wv = Wm[row * K_LNK + lane];
        iv = ((b << 12) | cols[s * K_LNK + lane]) << 5;
    }

    const float4* Vin4 = (const float4*)Vin;
    float4 acc = ((const float4*)g_Vres)[(row << 5) + lane];
    #pragma unroll
    for (int k = 0; k < K_LNK; ++k) {
        float wk = __shfl_sync(0xffffffffu, wv, k);
        int   ik = __shfl_sync(0xffffffffu, iv, k);
        float4 v = Vin4[ik + lane];
        acc.x += wk * v.x; acc.y += wk * v.y;
        acc.z += wk * v.z; acc.w += wk * v.w;
    }
    ((float4*)Vout)[(row << 5) + lane] = acc;
}

// ---------------------------------------------------------------------------
extern "C" void kernel_launch(void* const* d_in, const int* in_sizes, int n_in,
                              void* d_out, int out_size) {
    const int*   data = (const int*)  d_in[0];
    const int*   cols = (const int*)  d_in[1];
    const float* emb  = (const float*)d_in[2];
    const float* apc  = (const float*)d_in[3];
    const float* gW1  = (const float*)d_in[4];
    const float* gb1  = (const float*)d_in[5];
    const float* gW2  = (const float*)d_in[6];
    const float* gb2  = (const float*)d_in[7];
    const float* fW1  = (const float*)d_in[8];
    const float* fb1  = (const float*)d_in[9];
    const float* fW2  = (const float*)d_in[10];
    const float* fb2  = (const float*)d_in[11];
    float* out = (float*)d_out;

    cudaFuncSetAttribute(k_mlp, cudaFuncAttributeMaxDynamicSharedMemorySize,
                         SMEM_MLP);

    // 1) weight prep (transpose + bf16 split)
    k_prep<<<(PREP_TOT + 255) / 256, 256>>>(gW1, gW2, fW1, fW2);

    // 2) embeddings -> bf16 hi/lo
    k_embed<<<(R_TOT * 16) / 256, 256>>>(data, emb, apc);

    // 3) all 13 fused MLPs on warp tensor cores
    dim3 grid_mlp(R_TOT / 128, 13);
    k_mlp<<<grid_mlp, 512, SMEM_MLP>>>(gb1, gb2, fb1, fb2);

    // 4) 12 chord-mix scan steps
    for (int m = 0; m < M_NET; ++m)
        k_scan<<<R_TOT / 8, 256>>>(m, cols, out);
}

// round 9
// speedup vs baseline: 2.6002x; 1.1009x over previous
#include <cuda_runtime.h>
#include <cuda_bf16.h>
#include <math.h>
#include <stdint.h>

#define R_TOT 16384
#define S_LEN 4096
#define D_DIM 128
#define K_LNK 13
#define M_NET 12

typedef unsigned int u32;
typedef unsigned long long u64;

// ---------------- scratch (static device memory only) ----------------------
__device__ __nv_bfloat16 g_Xhi[R_TOT * D_DIM];          // X hi, row-major
__device__ __nv_bfloat16 g_Xlo[R_TOT * D_DIM];          // X lo
__device__ __nv_bfloat16 g_B1hi[13 * 128 * 128];        // W1^T [net][n][k]
__device__ __nv_bfloat16 g_B1lo[13 * 128 * 128];
__device__ __nv_bfloat16 g_B2ghi[128 * 128];            // gW2^T [n][k]
__device__ __nv_bfloat16 g_B2glo[128 * 128];
__device__ __nv_bfloat16 g_B2fhi[12 * 16 * 128];        // fW2^T padded N=16
__device__ __nv_bfloat16 g_B2flo[12 * 16 * 128];
__device__ float g_Vres[R_TOT * D_DIM];                 // fp32 residual (exact)
__device__ __nv_bfloat16 g_Vbf0[R_TOT * D_DIM];         // bf16 V mirror ping
__device__ __nv_bfloat16 g_Vbf1[R_TOT * D_DIM];         // bf16 V mirror pong
__device__ float g_Wall[M_NET * R_TOT * K_LNK];

// ---------------- helpers ---------------------------------------------------
__device__ __forceinline__ u32 smem_u32(const void* p) {
    u32 a;
    asm("{ .reg .u64 t; cvta.to.shared.u64 t, %1; cvt.u32.u64 %0, t; }"
        : "=r"(a) : "l"(p));
    return a;
}
__device__ __forceinline__ void ldsm4(u32* r, u32 addr) {
    asm volatile("ldmatrix.sync.aligned.m8n8.x4.shared.b16 {%0,%1,%2,%3}, [%4];"
        : "=r"(r[0]), "=r"(r[1]), "=r"(r[2]), "=r"(r[3]) : "r"(addr));
}
__device__ __forceinline__ void mma16816(float* d, const u32* a, const u32* b) {
    asm volatile(
        "mma.sync.aligned.m16n8k16.row.col.f32.bf16.bf16.f32 "
        "{%0,%1,%2,%3}, {%4,%5,%6,%7}, {%8,%9}, {%0,%1,%2,%3};"
        : "+f"(d[0]), "+f"(d[1]), "+f"(d[2]), "+f"(d[3])
        : "r"(a[0]), "r"(a[1]), "r"(a[2]), "r"(a[3]), "r"(b[0]), "r"(b[1]));
}
// swizzled byte address of 16B unit (r, c16) in a [rows][128]bf16 smem tile
__device__ __forceinline__ u32 sw_addr(u32 base, int r, int c16) {
    return base + (u32)(((r << 4) + (c16 ^ (r & 7))) << 4);
}
__device__ __forceinline__ void bf_split(float v, unsigned short& h,
                                         unsigned short& l) {
    __nv_bfloat16 hb = __float2bfloat16(v);
    __nv_bfloat16 lb = __float2bfloat16(v - __bfloat162float(hb));
    h = __bfloat16_as_ushort(hb);
    l = __bfloat16_as_ushort(lb);
}
// pack two fp32 -> bf16x2 (lo in low half, hi in high half; mem order lo first)
__device__ __forceinline__ u32 pack_bf16x2(float lo, float hi) {
    u32 r;
    asm("cvt.rn.bf16x2.f32 %0, %1, %2;" : "=r"(r) : "f"(hi), "f"(lo));
    return r;
}
__device__ __forceinline__ float gelu_exact(float x) {
    return 0.5f * x * (1.0f + erff(x * 0.70710678118654752440f));
}

// ---------------------------------------------------------------------------
// Prep: transpose + bf16-split weights into [n][k] row-major hi/lo.
// ---------------------------------------------------------------------------
#define PREP_A (13 * 128 * 64)
#define PREP_B (128 * 64)
#define PREP_C (12 * 16 * 64)
#define PREP_TOT (PREP_A + PREP_B + PREP_C)

__global__ void k_prep(const float* __restrict__ gW1,
                       const float* __restrict__ gW2,
                       const float* __restrict__ fW1,
                       const float* __restrict__ fW2) {
    int t = blockIdx.x * blockDim.x + threadIdx.x;
    if (t >= PREP_TOT) return;

    float w0, w1;
    u32* dh;
    u32* dl;
    int widx;
    if (t < PREP_A) {
        int net = t >> 13;                 // /8192
        int r = t & 8191;
        int n = r >> 6, k = (r & 63) * 2;
        const float* W1 = (net == 0) ? gW1 : fW1 + (size_t)(net - 1) * 128 * 128;
        w0 = W1[k * 128 + n];
        w1 = W1[(k + 1) * 128 + n];
        widx = (net * 128 + n) * 64 + (k >> 1);
        dh = (u32*)g_B1hi; dl = (u32*)g_B1lo;
    } else if (t < PREP_A + PREP_B) {
        int r = t - PREP_A;
        int n = r >> 6, k = (r & 63) * 2;
        w0 = gW2[k * 128 + n];
        w1 = gW2[(k + 1) * 128 + n];
        widx = n * 64 + (k >> 1);
        dh = (u32*)g_B2ghi; dl = (u32*)g_B2glo;
    } else {
        int r = t - PREP_A - PREP_B;
        int net = r >> 10;                 // /1024
        int rr = r & 1023;
        int n = rr >> 6, k = (rr & 63) * 2;
        w0 = (n < 13) ? fW2[(size_t)net * 128 * 13 + k * 13 + n] : 0.0f;
        w1 = (n < 13) ? fW2[(size_t)net * 128 * 13 + (k + 1) * 13 + n] : 0.0f;
        widx = (net * 16 + n) * 64 + (k >> 1);
        dh = (u32*)g_B2fhi; dl = (u32*)g_B2flo;
    }
    unsigned short h0, l0, h1, l1;
    bf_split(w0, h0, l0);
    bf_split(w1, h1, l1);
    dh[widx] = (u32)h0 | ((u32)h1 << 16);
    dl[widx] = (u32)l0 | ((u32)l1 << 16);
}

// ---------------------------------------------------------------------------
// Embed: x = emb[data] + apc -> bf16 hi/lo row-major.
// ---------------------------------------------------------------------------
__global__ void k_embed(const int* __restrict__ data,
                        const float* __restrict__ emb,
                        const float* __restrict__ apc) {
    int idx = blockIdx.x * blockDim.x + threadIdx.x;   // R_TOT*16 threads
    int row = idx >> 4;
    int g8 = idx & 15;
    int tok = data[row];
    int s = row & (S_LEN - 1);
    float4 e0 = ((const float4*)emb)[tok * 32 + g8 * 2];
    float4 e1 = ((const float4*)emb)[tok * 32 + g8 * 2 + 1];
    float4 a0 = ((const float4*)apc)[s * 32 + g8 * 2];
    float4 a1 = ((const float4*)apc)[s * 32 + g8 * 2 + 1];
    float v[8] = {e0.x + a0.x, e0.y + a0.y, e0.z + a0.z, e0.w + a0.w,
                  e1.x + a1.x, e1.y + a1.y, e1.z + a1.z, e1.w + a1.w};
    u32 hp[4], lp[4];
    #pragma unroll
    for (int p = 0; p < 4; ++p) {
        unsigned short h0, l0, h1, l1;
        bf_split(v[2 * p], h0, l0);
        bf_split(v[2 * p + 1], h1, l1);
        hp[p] = (u32)h0 | ((u32)h1 << 16);
        lp[p] = (u32)l0 | ((u32)l1 << 16);
    }
    ((uint4*)g_Xhi)[row * 16 + g8] = make_uint4(hp[0], hp[1], hp[2], hp[3]);
    ((uint4*)g_Xlo)[row * 16 + g8] = make_uint4(lp[0], lp[1], lp[2], lp[3]);
}

// ---------------------------------------------------------------------------
// k_mlp: warp-MMA (mma.sync bf16 hi/lo split) fused 2-layer MLP.
// grid = (128 row-tiles, 13 nets), 512 threads (16 warps, warp tile 32x32).
// m==0 epilogue writes fp32 g_Vres AND bf16 mirror g_Vbf0.
// ---------------------------------------------------------------------------
#define SM_W1HI  0
#define SM_W1LO  32768
#define SM_XHHI  65536
#define SM_XHLO  98304
#define SM_F2HI  131072
#define SM_F2LO  135168
#define SM_B1S   139264
#define SM_B2S   139776
#define SMEM_MLP 140288

extern __shared__ char smc[];

__global__ void __launch_bounds__(512, 1) k_mlp(
    const float* __restrict__ gb1, const float* __restrict__ gb2,
    const float* __restrict__ fb1, const float* __restrict__ fb2) {
    const int tid = threadIdx.x;
    const int lane = tid & 31;
    const int wid = tid >> 5;
    const int m = blockIdx.y;
    const int row0 = blockIdx.x * 128;
    const u32 sbase = smem_u32(smc);
    float* b1s = (float*)(smc + SM_B1S);
    float* b2s = (float*)(smc + SM_B2S);

    // ---- stage W1^T hi/lo and X hi/lo into swizzled smem ----
    {
        const uint4* s1h = (const uint4*)g_B1hi + m * 2048;
        const uint4* s1l = (const uint4*)g_B1lo + m * 2048;
        const uint4* sxh = (const uint4*)g_Xhi + row0 * 16;
        const uint4* sxl = (const uint4*)g_Xlo + row0 * 16;
        #pragma unroll
        for (int p = 0; p < 4; ++p) {
            int q = tid + p * 512;
            int r = q >> 4, c16 = q & 15;
            u32 d = (u32)(((r << 4) + (c16 ^ (r & 7))) << 4);
            *(uint4*)(smc + SM_W1HI + d) = s1h[q];
            *(uint4*)(smc + SM_W1LO + d) = s1l[q];
            *(uint4*)(smc + SM_XHHI + d) = sxh[q];
            *(uint4*)(smc + SM_XHLO + d) = sxl[q];
        }
    }
    if (m > 0) {
        const uint4* sfh = (const uint4*)g_B2fhi + (m - 1) * 256;
        const uint4* sfl = (const uint4*)g_B2flo + (m - 1) * 256;
        if (tid < 256) {
            int r = tid >> 4, c16 = tid & 15;
            u32 d = (u32)(((r << 4) + (c16 ^ (r & 7))) << 4);
            *(uint4*)(smc + SM_F2HI + d) = sfh[tid];
            *(uint4*)(smc + SM_F2LO + d) = sfl[tid];
        }
        if (tid < 128) b1s[tid] = fb1[(m - 1) * 128 + tid];
        if (tid < 16)  b2s[tid] = (tid < 13) ? fb2[(m - 1) * 13 + tid] : 0.0f;
    } else {
        if (tid < 128) { b1s[tid] = gb1[tid]; b2s[tid] = gb2[tid]; }
    }
    __syncthreads();

    // fragment lane offsets
    const int a_ro = (lane & 7) + (lane & 8);
    const int a_co = lane >> 4;
    const int b_ro = (lane & 7) + ((lane >> 1) & 8);
    const int b_co = (lane >> 3) & 1;
    const int tq = lane >> 2;
    const int tr = (lane & 3) * 2;

    const int wm = (wid & 3) * 32;    // warp M offset
    const int wn = (wid >> 2) * 32;   // warp N offset

    // ================= Layer 1: H = gelu(X @ W1 + b1) ======================
    float acc[2][4][4];
    #pragma unroll
    for (int i = 0; i < 2; ++i)
        #pragma unroll
        for (int j = 0; j < 4; ++j)
            #pragma unroll
            for (int q = 0; q < 4; ++q) acc[i][j][q] = 0.0f;

    #pragma unroll
    for (int k = 0; k < 8; ++k) {
        const int kc = k * 2;
        u32 ah[2][4], al[2][4], bh[2][4], bl[2][4];
        #pragma unroll
        for (int mt = 0; mt < 2; ++mt) {
            int r = wm + mt * 16 + a_ro;
            ldsm4(ah[mt], sw_addr(sbase + SM_XHHI, r, kc + a_co));
            ldsm4(al[mt], sw_addr(sbase + SM_XHLO, r, kc + a_co));
        }
        #pragma unroll
        for (int ng = 0; ng < 2; ++ng) {
            int r = wn + ng * 16 + b_ro;
            ldsm4(bh[ng], sw_addr(sbase + SM_W1HI, r, kc + b_co));
            ldsm4(bl[ng], sw_addr(sbase + SM_W1LO, r, kc + b_co));
        }
        #pragma unroll
        for (int mt = 0; mt < 2; ++mt)
            #pragma unroll
            for (int ng = 0; ng < 2; ++ng) {
                mma16816(acc[mt][2 * ng],     ah[mt], &bh[ng][0]);
                mma16816(acc[mt][2 * ng + 1], ah[mt], &bh[ng][2]);
                mma16816(acc[mt][2 * ng],     ah[mt], &bl[ng][0]);
                mma16816(acc[mt][2 * ng + 1], ah[mt], &bl[ng][2]);
                mma16816(acc[mt][2 * ng],     al[mt], &bh[ng][0]);
                mma16816(acc[mt][2 * ng + 1], al[mt], &bh[ng][2]);
            }
    }
    __syncthreads();   // everyone done reading X before H overwrites it

    // epilogue 1: bias + gelu + bf16 split, H -> XH region
    #pragma unroll
    for (int mt = 0; mt < 2; ++mt)
        #pragma unroll
        for (int nt = 0; nt < 4; ++nt) {
            int r = wm + mt * 16 + tq;
            int c = wn + nt * 8 + tr;
            float v0 = gelu_exact(acc[mt][nt][0] + b1s[c]);
            float v1 = gelu_exact(acc[mt][nt][1] + b1s[c + 1]);
            float v2 = gelu_exact(acc[mt][nt][2] + b1s[c]);
            float v3 = gelu_exact(acc[mt][nt][3] + b1s[c + 1]);
            unsigned short h0, l0, h1, l1, h2, l2, h3, l3;
            bf_split(v0, h0, l0); bf_split(v1, h1, l1);
            bf_split(v2, h2, l2); bf_split(v3, h3, l3);
            int c16 = c >> 3, cb = (c & 7) * 2;
            u32 d0 = sw_addr(sbase + SM_XHHI, r, c16) - sbase + cb;
            u32 d8 = sw_addr(sbase + SM_XHHI, r + 8, c16) - sbase + cb;
            *(u32*)(smc + d0) = (u32)h0 | ((u32)h1 << 16);
            *(u32*)(smc + d8) = (u32)h2 | ((u32)h3 << 16);
            d0 += (SM_XHLO - SM_XHHI); d8 += (SM_XHLO - SM_XHHI);
            *(u32*)(smc + d0) = (u32)l0 | ((u32)l1 << 16);
            *(u32*)(smc + d8) = (u32)l2 | ((u32)l3 << 16);
        }

    // m==0: restage gW2^T over the consumed W1 region
    if (m == 0) {
        const uint4* s2h = (const uint4*)g_B2ghi;
        const uint4* s2l = (const uint4*)g_B2glo;
        #pragma unroll
        for (int p = 0; p < 4; ++p) {
            int q = tid + p * 512;
            int r = q >> 4, c16 = q & 15;
            u32 d = (u32)(((r << 4) + (c16 ^ (r & 7))) << 4);
            *(uint4*)(smc + SM_W1HI + d) = s2h[q];
            *(uint4*)(smc + SM_W1LO + d) = s2l[q];
        }
    }
    __syncthreads();

    // ================= Layer 2 =============================================
    if (m == 0) {
        float ac2[2][4][4];
        #pragma unroll
        for (int i = 0; i < 2; ++i)
            #pragma unroll
            for (int j = 0; j < 4; ++j)
                #pragma unroll
                for (int q = 0; q < 4; ++q) ac2[i][j][q] = 0.0f;
        #pragma unroll
        for (int k = 0; k < 8; ++k) {
            const int kc = k * 2;
            u32 ah[2][4], al[2][4], bh[2][4], bl[2][4];
            #pragma unroll
            for (int mt = 0; mt < 2; ++mt) {
                int r = wm + mt * 16 + a_ro;
                ldsm4(ah[mt], sw_addr(sbase + SM_XHHI, r, kc + a_co));
                ldsm4(al[mt], sw_addr(sbase + SM_XHLO, r, kc + a_co));
            }
            #pragma unroll
            for (int ng = 0; ng < 2; ++ng) {
                int r = wn + ng * 16 + b_ro;
                ldsm4(bh[ng], sw_addr(sbase + SM_W1HI, r, kc + b_co));
                ldsm4(bl[ng], sw_addr(sbase + SM_W1LO, r, kc + b_co));
            }
            #pragma unroll
            for (int mt = 0; mt < 2; ++mt)
                #pragma unroll
                for (int ng = 0; ng < 2; ++ng) {
                    mma16816(ac2[mt][2 * ng],     ah[mt], &bh[ng][0]);
                    mma16816(ac2[mt][2 * ng + 1], ah[mt], &bh[ng][2]);
                    mma16816(ac2[mt][2 * ng],     ah[mt], &bl[ng][0]);
                    mma16816(ac2[mt][2 * ng + 1], ah[mt], &bl[ng][2]);
                    mma16816(ac2[mt][2 * ng],     al[mt], &bh[ng][0]);
                    mma16816(ac2[mt][2 * ng + 1], al[mt], &bh[ng][2]);
                }
        }
        #pragma unroll
        for (int mt = 0; mt < 2; ++mt)
            #pragma unroll
            for (int nt = 0; nt < 4; ++nt) {
                int r = wm + mt * 16 + tq;
                int c = wn + nt * 8 + tr;
                float2 o0 = make_float2(ac2[mt][nt][0] + b2s[c],
                                        ac2[mt][nt][1] + b2s[c + 1]);
                float2 o1 = make_float2(ac2[mt][nt][2] + b2s[c],
                                        ac2[mt][nt][3] + b2s[c + 1]);
                *(float2*)(g_Vres + (size_t)(row0 + r) * 128 + c) = o0;
                *(float2*)(g_Vres + (size_t)(row0 + r + 8) * 128 + c) = o1;
                // bf16 mirror seed for the scan gathers
                *(u32*)((__nv_bfloat16*)g_Vbf0 + (size_t)(row0 + r) * 128 + c) =
                    pack_bf16x2(o0.x, o0.y);
                *(u32*)((__nv_bfloat16*)g_Vbf0 + (size_t)(row0 + r + 8) * 128 + c) =
                    pack_bf16x2(o1.x, o1.y);
            }
    } else if (wid < 8) {
        const int wm2 = wid * 16;
        float ac2[2][4];
        #pragma unroll
        for (int j = 0; j < 2; ++j)
            #pragma unroll
            for (int q = 0; q < 4; ++q) ac2[j][q] = 0.0f;
        #pragma unroll
        for (int k = 0; k < 8; ++k) {
            const int kc = k * 2;
            u32 ah[4], al[4], bh[4], bl[4];
            int r = wm2 + a_ro;
            ldsm4(ah, sw_addr(sbase + SM_XHHI, r, kc + a_co));
            ldsm4(al, sw_addr(sbase + SM_XHLO, r, kc + a_co));
            ldsm4(bh, sw_addr(sbase + SM_F2HI, b_ro, kc + b_co));
            ldsm4(bl, sw_addr(sbase + SM_F2LO, b_ro, kc + b_co));
            mma16816(ac2[0], ah, &bh[0]);
            mma16816(ac2[1], ah, &bh[2]);
            mma16816(ac2[0], ah, &bl[0]);
            mma16816(ac2[1], ah, &bl[2]);
            mma16816(ac2[0], al, &bh[0]);
            mma16816(ac2[1], al, &bh[2]);
        }
        float* op = g_Wall + (size_t)(m - 1) * R_TOT * K_LNK
                           + (size_t)row0 * K_LNK;
        #pragma unroll
        for (int nt = 0; nt < 2; ++nt) {
            int c = nt * 8 + tr;
            int r = wm2 + tq;
            if (c < 13) {
                op[(r) * K_LNK + c]     = ac2[nt][0] + b2s[c];
                op[(r + 8) * K_LNK + c] = ac2[nt][2] + b2s[c];
            }
            if (c + 1 < 13) {
                op[(r) * K_LNK + c + 1]     = ac2[nt][1] + b2s[c + 1];
                op[(r + 8) * K_LNK + c + 1] = ac2[nt][3] + b2s[c + 1];
            }
        }
    }
}

// ---------------------------------------------------------------------------
// k_scan: one chord-mix step with bf16 gathers (halved L2 traffic).
// Vout = sum_k W[row,k] * bf16(V)[cols[row,k]] + Vres[row] (fp32 acc).
// Intermediate steps write only the bf16 mirror; final step writes fp32 out.
// One warp per row; 4 elems (uint2 of bf16) per lane; shfl broadcast.
// ---------------------------------------------------------------------------
__global__ void __launch_bounds__(256) k_scan(int m, const int* __restrict__ cols,
                                              float* __restrict__ out_final) {
    const __nv_bfloat16* Vin = (m & 1) ? g_Vbf1 : g_Vbf0;
    __nv_bfloat16* Vout = ((m + 1) & 1) ? g_Vbf1 : g_Vbf0;
    const float* Wm = g_Wall + (size_t)m * R_TOT * K_LNK;

    const int lane = threadIdx.x & 31;
    const int row  = (blockIdx.x * blockDim.x + threadIdx.x) >> 5;
    const int s    = row & (S_LEN - 1);
    const int b    = row >> 12;

    float wv = 0.0f; int iv = 0;
    if (lane < K_LNK) {
        wv = Wm[row * K_LNK + lane];
        iv = ((b << 12) | cols[s * K_LNK + lane]) << 5;   // uint2 row base (32/row)
    }

    const uint2* Vin2 = (const uint2*)Vin;
    float4 acc = ((const float4*)g_Vres)[(row << 5) + lane];
    #pragma unroll
    for (int k = 0; k < K_LNK; ++k) {
        float wk = __shfl_sync(0xffffffffu, wv, k);
        int   ik = __shfl_sync(0xffffffffu, iv, k);
        uint2 v = Vin2[ik + lane];
        float f0 = __uint_as_float(v.x << 16);
        float f1 = __uint_as_float(v.x & 0xFFFF0000u);
        float f2 = __uint_as_float(v.y << 16);
        float f3 = __uint_as_float(v.y & 0xFFFF0000u);
        acc.x += wk * f0; acc.y += wk * f1;
        acc.z += wk * f2; acc.w += wk * f3;
    }
    if (m == M_NET - 1) {
        ((float4*)out_final)[(row << 5) + lane] = acc;
    } else {
        uint2 o;
        o.x = pack_bf16x2(acc.x, acc.y);
        o.y = pack_bf16x2(acc.z, acc.w);
        ((uint2*)Vout)[(row << 5) + lane] = o;
    }
}

// ---------------------------------------------------------------------------
extern "C" void kernel_launch(void* const* d_in, const int* in_sizes, int n_in,
                              void* d_out, int out_size) {
    const int*   data = (const int*)  d_in[0];
    const int*   cols = (const int*)  d_in[1];
    const float* emb  = (const float*)d_in[2];
    const float* apc  = (const float*)d_in[3];
    const float* gW1  = (const float*)d_in[4];
    const float* gb1  = (const float*)d_in[5];
    const float* gW2  = (const float*)d_in[6];
    const float* gb2  = (const float*)d_in[7];
    const float* fW1  = (const float*)d_in[8];
    const float* fb1  = (const float*)d_in[9];
    const float* fW2  = (const float*)d_in[10];
    const float* fb2  = (const float*)d_in[11];
    float* out = (float*)d_out;

    cudaFuncSetAttribute(k_mlp, cudaFuncAttributeMaxDynamicSharedMemorySize,
                         SMEM_MLP);

    // 1) weight prep (transpose + bf16 split)
    k_prep<<<(PREP_TOT + 255) / 256, 256>>>(gW1, gW2, fW1, fW2);

    // 2) embeddings -> bf16 hi/lo
    k_embed<<<(R_TOT * 16) / 256, 256>>>(data, emb, apc);

    // 3) all 13 fused MLPs on warp tensor cores
    dim3 grid_mlp(R_TOT / 128, 13);
    k_mlp<<<grid_mlp, 512, SMEM_MLP>>>(gb1, gb2, fb1, fb2);

    // 4) 12 chord-mix scan steps (bf16 gathers, fp32 accumulate)
    for (int m = 0; m < M_NET; ++m)
        k_scan<<<R_TOT / 8, 256>>>(m, cols, out);
}

// round 10
// speedup vs baseline: 3.3309x; 1.2810x over previous
#include <cuda_runtime.h>
#include <cuda_bf16.h>
#include <math.h>
#include <stdint.h>

#define R_TOT 16384
#define S_LEN 4096
#define D_DIM 128
#define K_LNK 13
#define M_NET 12

typedef unsigned int u32;
typedef unsigned long long u64;

// ---------------- scratch (static device memory only) ----------------------
__device__ __nv_bfloat16 g_Xhi[R_TOT * D_DIM];          // X hi, row-major
__device__ __nv_bfloat16 g_Xlo[R_TOT * D_DIM];          // X lo
__device__ __nv_bfloat16 g_B1hi[13 * 128 * 128];        // W1^T [net][n][k]
__device__ __nv_bfloat16 g_B1lo[13 * 128 * 128];
__device__ __nv_bfloat16 g_B2ghi[128 * 128];            // gW2^T [n][k]
__device__ __nv_bfloat16 g_B2glo[128 * 128];
__device__ __nv_bfloat16 g_B2fhi[12 * 16 * 128];        // fW2^T padded N=16
__device__ float g_Vres[R_TOT * D_DIM];                 // fp32 residual (exact)
__device__ __nv_bfloat16 g_Vbf0[R_TOT * D_DIM];         // bf16 V mirror ping
__device__ __nv_bfloat16 g_Vbf1[R_TOT * D_DIM];         // bf16 V mirror pong
__device__ float g_Wall[M_NET * R_TOT * K_LNK];

// ---------------- helpers ---------------------------------------------------
__device__ __forceinline__ u32 smem_u32(const void* p) {
    u32 a;
    asm("{ .reg .u64 t; cvta.to.shared.u64 t, %1; cvt.u32.u64 %0, t; }"
        : "=r"(a) : "l"(p));
    return a;
}
__device__ __forceinline__ void ldsm4(u32* r, u32 addr) {
    asm volatile("ldmatrix.sync.aligned.m8n8.x4.shared.b16 {%0,%1,%2,%3}, [%4];"
        : "=r"(r[0]), "=r"(r[1]), "=r"(r[2]), "=r"(r[3]) : "r"(addr));
}
__device__ __forceinline__ void mma16816(float* d, const u32* a, const u32* b) {
    asm volatile(
        "mma.sync.aligned.m16n8k16.row.col.f32.bf16.bf16.f32 "
        "{%0,%1,%2,%3}, {%4,%5,%6,%7}, {%8,%9}, {%0,%1,%2,%3};"
        : "+f"(d[0]), "+f"(d[1]), "+f"(d[2]), "+f"(d[3])
        : "r"(a[0]), "r"(a[1]), "r"(a[2]), "r"(a[3]), "r"(b[0]), "r"(b[1]));
}
// swizzled byte address of 16B unit (r, c16) in a [rows][128]bf16 smem tile
__device__ __forceinline__ u32 sw_addr(u32 base, int r, int c16) {
    return base + (u32)(((r << 4) + (c16 ^ (r & 7))) << 4);
}
__device__ __forceinline__ void bf_split(float v, unsigned short& h,
                                         unsigned short& l) {
    __nv_bfloat16 hb = __float2bfloat16(v);
    __nv_bfloat16 lb = __float2bfloat16(v - __bfloat162float(hb));
    h = __bfloat16_as_ushort(hb);
    l = __bfloat16_as_ushort(lb);
}
// pack two fp32 -> bf16x2 (lo arg in low half = memory-first element)
__device__ __forceinline__ u32 pack_bf16x2(float lo, float hi) {
    u32 r;
    asm("cvt.rn.bf16x2.f32 %0, %1, %2;" : "=r"(r) : "f"(hi), "f"(lo));
    return r;
}
__device__ __forceinline__ float gelu_exact(float x) {
    return 0.5f * x * (1.0f + erff(x * 0.70710678118654752440f));
}

// ---------------------------------------------------------------------------
// Prep: transpose + bf16-split weights into [n][k] row-major hi/lo.
// ---------------------------------------------------------------------------
#define PREP_A (13 * 128 * 64)
#define PREP_B (128 * 64)
#define PREP_C (12 * 16 * 64)
#define PREP_TOT (PREP_A + PREP_B + PREP_C)

__global__ void k_prep(const float* __restrict__ gW1,
                       const float* __restrict__ gW2,
                       const float* __restrict__ fW1,
                       const float* __restrict__ fW2) {
    int t = blockIdx.x * blockDim.x + threadIdx.x;
    if (t >= PREP_TOT) return;

    float w0, w1;
    if (t < PREP_A) {
        int net = t >> 13;
        int r = t & 8191;
        int n = r >> 6, k = (r & 63) * 2;
        const float* W1 = (net == 0) ? gW1 : fW1 + (size_t)(net - 1) * 128 * 128;
        w0 = W1[k * 128 + n];
        w1 = W1[(k + 1) * 128 + n];
        int widx = (net * 128 + n) * 64 + (k >> 1);
        unsigned short h0, l0, h1, l1;
        bf_split(w0, h0, l0); bf_split(w1, h1, l1);
        ((u32*)g_B1hi)[widx] = (u32)h0 | ((u32)h1 << 16);
        ((u32*)g_B1lo)[widx] = (u32)l0 | ((u32)l1 << 16);
    } else if (t < PREP_A + PREP_B) {
        int r = t - PREP_A;
        int n = r >> 6, k = (r & 63) * 2;
        w0 = gW2[k * 128 + n];
        w1 = gW2[(k + 1) * 128 + n];
        int widx = n * 64 + (k >> 1);
        unsigned short h0, l0, h1, l1;
        bf_split(w0, h0, l0); bf_split(w1, h1, l1);
        ((u32*)g_B2ghi)[widx] = (u32)h0 | ((u32)h1 << 16);
        ((u32*)g_B2glo)[widx] = (u32)l0 | ((u32)l1 << 16);
    } else {
        int r = t - PREP_A - PREP_B;
        int net = r >> 10;
        int rr = r & 1023;
        int n = rr >> 6, k = (rr & 63) * 2;
        w0 = (n < 13) ? fW2[(size_t)net * 128 * 13 + k * 13 + n] : 0.0f;
        w1 = (n < 13) ? fW2[(size_t)net * 128 * 13 + (k + 1) * 13 + n] : 0.0f;
        ((u32*)g_B2fhi)[(net * 16 + n) * 64 + (k >> 1)] =
            pack_bf16x2(w0, w1);
    }
}

// ---------------------------------------------------------------------------
// Embed: x = emb[data] + apc -> bf16 hi/lo row-major.
// ---------------------------------------------------------------------------
__global__ void k_embed(const int* __restrict__ data,
                        const float* __restrict__ emb,
                        const float* __restrict__ apc) {
    int idx = blockIdx.x * blockDim.x + threadIdx.x;   // R_TOT*16 threads
    int row = idx >> 4;
    int g8 = idx & 15;
    int tok = data[row];
    int s = row & (S_LEN - 1);
    float4 e0 = ((const float4*)emb)[tok * 32 + g8 * 2];
    float4 e1 = ((const float4*)emb)[tok * 32 + g8 * 2 + 1];
    float4 a0 = ((const float4*)apc)[s * 32 + g8 * 2];
    float4 a1 = ((const float4*)apc)[s * 32 + g8 * 2 + 1];
    float v[8] = {e0.x + a0.x, e0.y + a0.y, e0.z + a0.z, e0.w + a0.w,
                  e1.x + a1.x, e1.y + a1.y, e1.z + a1.z, e1.w + a1.w};
    u32 hp[4], lp[4];
    #pragma unroll
    for (int p = 0; p < 4; ++p) {
        unsigned short h0, l0, h1, l1;
        bf_split(v[2 * p], h0, l0);
        bf_split(v[2 * p + 1], h1, l1);
        hp[p] = (u32)h0 | ((u32)h1 << 16);
        lp[p] = (u32)l0 | ((u32)l1 << 16);
    }
    ((uint4*)g_Xhi)[row * 16 + g8] = make_uint4(hp[0], hp[1], hp[2], hp[3]);
    ((uint4*)g_Xlo)[row * 16 + g8] = make_uint4(lp[0], lp[1], lp[2], lp[3]);
}

// ---------------------------------------------------------------------------
// k_mlp: warp-MMA fused 2-layer MLP.
// m==0 (g-net): 3-term bf16 hi/lo split (feeds the fp32 backbone).
// m>=1 (f-nets): single-term plain bf16 (W_all sensitivity ~7e-4 -> safe).
// grid = (128 row-tiles, 13 nets), 512 threads (16 warps, warp tile 32x32).
// ---------------------------------------------------------------------------
#define SM_W1HI  0
#define SM_W1LO  32768
#define SM_XHHI  65536
#define SM_XHLO  98304
#define SM_F2HI  131072
#define SM_B1S   139264
#define SM_B2S   139776
#define SMEM_MLP 140288

extern __shared__ char smc[];

__global__ void __launch_bounds__(512, 1) k_mlp(
    const float* __restrict__ gb1, const float* __restrict__ gb2,
    const float* __restrict__ fb1, const float* __restrict__ fb2) {
    const int tid = threadIdx.x;
    const int lane = tid & 31;
    const int wid = tid >> 5;
    const int m = blockIdx.y;
    const int row0 = blockIdx.x * 128;
    const u32 sbase = smem_u32(smc);
    float* b1s = (float*)(smc + SM_B1S);
    float* b2s = (float*)(smc + SM_B2S);

    // ---- stage into swizzled smem (lo regions only for g-net) ----
    {
        const uint4* s1h = (const uint4*)g_B1hi + m * 2048;
        const uint4* s1l = (const uint4*)g_B1lo + m * 2048;
        const uint4* sxh = (const uint4*)g_Xhi + row0 * 16;
        const uint4* sxl = (const uint4*)g_Xlo + row0 * 16;
        #pragma unroll
        for (int p = 0; p < 4; ++p) {
            int q = tid + p * 512;
            int r = q >> 4, c16 = q & 15;
            u32 d = (u32)(((r << 4) + (c16 ^ (r & 7))) << 4);
            *(uint4*)(smc + SM_W1HI + d) = s1h[q];
            *(uint4*)(smc + SM_XHHI + d) = sxh[q];
            if (m == 0) {
                *(uint4*)(smc + SM_W1LO + d) = s1l[q];
                *(uint4*)(smc + SM_XHLO + d) = sxl[q];
            }
        }
    }
    if (m > 0) {
        const uint4* sfh = (const uint4*)g_B2fhi + (m - 1) * 256;
        if (tid < 256) {
            int r = tid >> 4, c16 = tid & 15;
            u32 d = (u32)(((r << 4) + (c16 ^ (r & 7))) << 4);
            *(uint4*)(smc + SM_F2HI + d) = sfh[tid];
        }
        if (tid < 128) b1s[tid] = fb1[(m - 1) * 128 + tid];
        if (tid < 16)  b2s[tid] = (tid < 13) ? fb2[(m - 1) * 13 + tid] : 0.0f;
    } else {
        if (tid < 128) { b1s[tid] = gb1[tid]; b2s[tid] = gb2[tid]; }
    }
    __syncthreads();

    // fragment lane offsets
    const int a_ro = (lane & 7) + (lane & 8);
    const int a_co = lane >> 4;
    const int b_ro = (lane & 7) + ((lane >> 1) & 8);
    const int b_co = (lane >> 3) & 1;
    const int tq = lane >> 2;
    const int tr = (lane & 3) * 2;

    const int wm = (wid & 3) * 32;    // warp M offset
    const int wn = (wid >> 2) * 32;   // warp N offset

    // ================= Layer 1: H = gelu(X @ W1 + b1) ======================
    float acc[2][4][4];
    #pragma unroll
    for (int i = 0; i < 2; ++i)
        #pragma unroll
        for (int j = 0; j < 4; ++j)
            #pragma unroll
            for (int q = 0; q < 4; ++q) acc[i][j][q] = 0.0f;

    if (m == 0) {
        #pragma unroll
        for (int k = 0; k < 8; ++k) {
            const int kc = k * 2;
            u32 ah[2][4], al[2][4], bh[2][4], bl[2][4];
            #pragma unroll
            for (int mt = 0; mt < 2; ++mt) {
                int r = wm + mt * 16 + a_ro;
                ldsm4(ah[mt], sw_addr(sbase + SM_XHHI, r, kc + a_co));
                ldsm4(al[mt], sw_addr(sbase + SM_XHLO, r, kc + a_co));
            }
            #pragma unroll
            for (int ng = 0; ng < 2; ++ng) {
                int r = wn + ng * 16 + b_ro;
                ldsm4(bh[ng], sw_addr(sbase + SM_W1HI, r, kc + b_co));
                ldsm4(bl[ng], sw_addr(sbase + SM_W1LO, r, kc + b_co));
            }
            #pragma unroll
            for (int mt = 0; mt < 2; ++mt)
                #pragma unroll
                for (int ng = 0; ng < 2; ++ng) {
                    mma16816(acc[mt][2 * ng],     ah[mt], &bh[ng][0]);
                    mma16816(acc[mt][2 * ng + 1], ah[mt], &bh[ng][2]);
                    mma16816(acc[mt][2 * ng],     ah[mt], &bl[ng][0]);
                    mma16816(acc[mt][2 * ng + 1], ah[mt], &bl[ng][2]);
                    mma16816(acc[mt][2 * ng],     al[mt], &bh[ng][0]);
                    mma16816(acc[mt][2 * ng + 1], al[mt], &bh[ng][2]);
                }
        }
    } else {
        #pragma unroll
        for (int k = 0; k < 8; ++k) {
            const int kc = k * 2;
            u32 ah[2][4], bh[2][4];
            #pragma unroll
            for (int mt = 0; mt < 2; ++mt)
                ldsm4(ah[mt], sw_addr(sbase + SM_XHHI, wm + mt * 16 + a_ro, kc + a_co));
            #pragma unroll
            for (int ng = 0; ng < 2; ++ng)
                ldsm4(bh[ng], sw_addr(sbase + SM_W1HI, wn + ng * 16 + b_ro, kc + b_co));
            #pragma unroll
            for (int mt = 0; mt < 2; ++mt)
                #pragma unroll
                for (int ng = 0; ng < 2; ++ng) {
                    mma16816(acc[mt][2 * ng],     ah[mt], &bh[ng][0]);
                    mma16816(acc[mt][2 * ng + 1], ah[mt], &bh[ng][2]);
                }
        }
    }
    __syncthreads();   // everyone done reading X before H overwrites it

    // epilogue 1: bias + gelu (+ split for g-net), H -> XH region
    #pragma unroll
    for (int mt = 0; mt < 2; ++mt)
        #pragma unroll
        for (int nt = 0; nt < 4; ++nt) {
            int r = wm + mt * 16 + tq;
            int c = wn + nt * 8 + tr;
            float v0 = gelu_exact(acc[mt][nt][0] + b1s[c]);
            float v1 = gelu_exact(acc[mt][nt][1] + b1s[c + 1]);
            float v2 = gelu_exact(acc[mt][nt][2] + b1s[c]);
            float v3 = gelu_exact(acc[mt][nt][3] + b1s[c + 1]);
            int c16 = c >> 3, cb = (c & 7) * 2;
            u32 d0 = sw_addr(sbase + SM_XHHI, r, c16) - sbase + cb;
            u32 d8 = sw_addr(sbase + SM_XHHI, r + 8, c16) - sbase + cb;
            if (m == 0) {
                unsigned short h0, l0, h1, l1, h2, l2, h3, l3;
                bf_split(v0, h0, l0); bf_split(v1, h1, l1);
                bf_split(v2, h2, l2); bf_split(v3, h3, l3);
                *(u32*)(smc + d0) = (u32)h0 | ((u32)h1 << 16);
                *(u32*)(smc + d8) = (u32)h2 | ((u32)h3 << 16);
                *(u32*)(smc + d0 + (SM_XHLO - SM_XHHI)) = (u32)l0 | ((u32)l1 << 16);
                *(u32*)(smc + d8 + (SM_XHLO - SM_XHHI)) = (u32)l2 | ((u32)l3 << 16);
            } else {
                *(u32*)(smc + d0) = pack_bf16x2(v0, v1);
                *(u32*)(smc + d8) = pack_bf16x2(v2, v3);
            }
        }

    // m==0: restage gW2^T over the consumed W1 region
    if (m == 0) {
        const uint4* s2h = (const uint4*)g_B2ghi;
        const uint4* s2l = (const uint4*)g_B2glo;
        #pragma unroll
        for (int p = 0; p < 4; ++p) {
            int q = tid + p * 512;
            int r = q >> 4, c16 = q & 15;
            u32 d = (u32)(((r << 4) + (c16 ^ (r & 7))) << 4);
            *(uint4*)(smc + SM_W1HI + d) = s2h[q];
            *(uint4*)(smc + SM_W1LO + d) = s2l[q];
        }
    }
    __syncthreads();

    // ================= Layer 2 =============================================
    if (m == 0) {
        float ac2[2][4][4];
        #pragma unroll
        for (int i = 0; i < 2; ++i)
            #pragma unroll
            for (int j = 0; j < 4; ++j)
                #pragma unroll
                for (int q = 0; q < 4; ++q) ac2[i][j][q] = 0.0f;
        #pragma unroll
        for (int k = 0; k < 8; ++k) {
            const int kc = k * 2;
            u32 ah[2][4], al[2][4], bh[2][4], bl[2][4];
            #pragma unroll
            for (int mt = 0; mt < 2; ++mt) {
                int r = wm + mt * 16 + a_ro;
                ldsm4(ah[mt], sw_addr(sbase + SM_XHHI, r, kc + a_co));
                ldsm4(al[mt], sw_addr(sbase + SM_XHLO, r, kc + a_co));
            }
            #pragma unroll
            for (int ng = 0; ng < 2; ++ng) {
                int r = wn + ng * 16 + b_ro;
                ldsm4(bh[ng], sw_addr(sbase + SM_W1HI, r, kc + b_co));
                ldsm4(bl[ng], sw_addr(sbase + SM_W1LO, r, kc + b_co));
            }
            #pragma unroll
            for (int mt = 0; mt < 2; ++mt)
                #pragma unroll
                for (int ng = 0; ng < 2; ++ng) {
                    mma16816(ac2[mt][2 * ng],     ah[mt], &bh[ng][0]);
                    mma16816(ac2[mt][2 * ng + 1], ah[mt], &bh[ng][2]);
                    mma16816(ac2[mt][2 * ng],     ah[mt], &bl[ng][0]);
                    mma16816(ac2[mt][2 * ng + 1], ah[mt], &bl[ng][2]);
                    mma16816(ac2[mt][2 * ng],     al[mt], &bh[ng][0]);
                    mma16816(ac2[mt][2 * ng + 1], al[mt], &bh[ng][2]);
                }
        }
        #pragma unroll
        for (int mt = 0; mt < 2; ++mt)
            #pragma unroll
            for (int nt = 0; nt < 4; ++nt) {
                int r = wm + mt * 16 + tq;
                int c = wn + nt * 8 + tr;
                float2 o0 = make_float2(ac2[mt][nt][0] + b2s[c],
                                        ac2[mt][nt][1] + b2s[c + 1]);
                float2 o1 = make_float2(ac2[mt][nt][2] + b2s[c],
                                        ac2[mt][nt][3] + b2s[c + 1]);
                *(float2*)(g_Vres + (size_t)(row0 + r) * 128 + c) = o0;
                *(float2*)(g_Vres + (size_t)(row0 + r + 8) * 128 + c) = o1;
                *(u32*)((__nv_bfloat16*)g_Vbf0 + (size_t)(row0 + r) * 128 + c) =
                    pack_bf16x2(o0.x, o0.y);
                *(u32*)((__nv_bfloat16*)g_Vbf0 + (size_t)(row0 + r + 8) * 128 + c) =
                    pack_bf16x2(o1.x, o1.y);
            }
    } else if (wid < 8) {
        const int wm2 = wid * 16;
        float ac2[2][4];
        #pragma unroll
        for (int j = 0; j < 2; ++j)
            #pragma unroll
            for (int q = 0; q < 4; ++q) ac2[j][q] = 0.0f;
        #pragma unroll
        for (int k = 0; k < 8; ++k) {
            const int kc = k * 2;
            u32 ah[4], bh[4];
            ldsm4(ah, sw_addr(sbase + SM_XHHI, wm2 + a_ro, kc + a_co));
            ldsm4(bh, sw_addr(sbase + SM_F2HI, b_ro, kc + b_co));
            mma16816(ac2[0], ah, &bh[0]);
            mma16816(ac2[1], ah, &bh[2]);
        }
        float* op = g_Wall + (size_t)(m - 1) * R_TOT * K_LNK
                           + (size_t)row0 * K_LNK;
        #pragma unroll
        for (int nt = 0; nt < 2; ++nt) {
            int c = nt * 8 + tr;
            int r = wm2 + tq;
            if (c < 13) {
                op[(r) * K_LNK + c]     = ac2[nt][0] + b2s[c];
                op[(r + 8) * K_LNK + c] = ac2[nt][2] + b2s[c];
            }
            if (c + 1 < 13) {
                op[(r) * K_LNK + c + 1]     = ac2[nt][1] + b2s[c + 1];
                op[(r + 8) * K_LNK + c + 1] = ac2[nt][3] + b2s[c + 1];
            }
        }
    }
}

// ---------------------------------------------------------------------------
// k_scan: chord-mix step. Mix accumulated in packed bf16x2 (fma.rn.bf16x2),
// fp32 residual added once at the end. One warp/row, uint2 (4 bf16) per lane.
// ---------------------------------------------------------------------------
__global__ void __launch_bounds__(256) k_scan(int m, const int* __restrict__ cols,
                                              float* __restrict__ out_final) {
    const __nv_bfloat16* Vin = (m & 1) ? g_Vbf1 : g_Vbf0;
    __nv_bfloat16* Vout = ((m + 1) & 1) ? g_Vbf1 : g_Vbf0;
    const float* Wm = g_Wall + (size_t)m * R_TOT * K_LNK;

    const int lane = threadIdx.x & 31;
    const int row  = (blockIdx.x * blockDim.x + threadIdx.x) >> 5;
    const int s    = row & (S_LEN - 1);
    const int b    = row >> 12;

    u32 wv = 0; int iv = 0;
    if (lane < K_LNK) {
        float w = Wm[row * K_LNK + lane];
        wv = pack_bf16x2(w, w);
        iv = ((b << 12) | cols[s * K_LNK + lane]) << 5;   // uint2 row base
    }

    float4 res = ((const float4*)g_Vres)[(row << 5) + lane];

    const uint2* Vin2 = (const uint2*)Vin;
    u32 acc0 = 0, acc1 = 0;                 // bf16x2 mix accumulators
    #pragma unroll
    for (int k = 0; k < K_LNK; ++k) {
        u32 wk = __shfl_sync(0xffffffffu, wv, k);
        int ik = __shfl_sync(0xffffffffu, iv, k);
        uint2 v = Vin2[ik + lane];
        asm("fma.rn.bf16x2 %0, %1, %2, %0;" : "+r"(acc0) : "r"(v.x), "r"(wk));
        asm("fma.rn.bf16x2 %0, %1, %2, %0;" : "+r"(acc1) : "r"(v.y), "r"(wk));
    }
    res.x += __uint_as_float(acc0 << 16);
    res.y += __uint_as_float(acc0 & 0xFFFF0000u);
    res.z += __uint_as_float(acc1 << 16);
    res.w += __uint_as_float(acc1 & 0xFFFF0000u);

    if (m == M_NET - 1) {
        ((float4*)out_final)[(row << 5) + lane] = res;
    } else {
        uint2 o;
        o.x = pack_bf16x2(res.x, res.y);
        o.y = pack_bf16x2(res.z, res.w);
        ((uint2*)Vout)[(row << 5) + lane] = o;
    }
}

// ---------------------------------------------------------------------------
extern "C" void kernel_launch(void* const* d_in, const int* in_sizes, int n_in,
                              void* d_out, int out_size) {
    const int*   data = (const int*)  d_in[0];
    const int*   cols = (const int*)  d_in[1];
    const float* emb  = (const float*)d_in[2];
    const float* apc  = (const float*)d_in[3];
    const float* gW1  = (const float*)d_in[4];
    const float* gb1  = (const float*)d_in[5];
    const float* gW2  = (const float*)d_in[6];
    const float* gb2  = (const float*)d_in[7];
    const float* fW1  = (const float*)d_in[8];
    const float* fb1  = (const float*)d_in[9];
    const float* fW2  = (const float*)d_in[10];
    const float* fb2  = (const float*)d_in[11];
    float* out = (float*)d_out;

    cudaFuncSetAttribute(k_mlp, cudaFuncAttributeMaxDynamicSharedMemorySize,
                         SMEM_MLP);

    // 1) weight prep (transpose + bf16 split)
    k_prep<<<(PREP_TOT + 255) / 256, 256>>>(gW1, gW2, fW1, fW2);

    // 2) embeddings -> bf16 hi/lo
    k_embed<<<(R_TOT * 16) / 256, 256>>>(data, emb, apc);

    // 3) all 13 fused MLPs on warp tensor cores
    dim3 grid_mlp(R_TOT / 128, 13);
    k_mlp<<<grid_mlp, 512, SMEM_MLP>>>(gb1, gb2, fb1, fb2);

    // 4) 12 chord-mix scan steps (bf16x2 mix accumulation)
    for (int m = 0; m < M_NET; ++m)
        k_scan<<<R_TOT / 8, 256>>>(m, cols, out);
}

// round 11
// speedup vs baseline: 3.5080x; 1.0532x over previous
#include <cuda_runtime.h>
#include <cuda_bf16.h>
#include <math.h>
#include <stdint.h>

#define R_TOT 16384
#define S_LEN 4096
#define D_DIM 128
#define K_LNK 13
#define M_NET 12

typedef unsigned int u32;
typedef unsigned long long u64;

// ---------------- scratch (static device memory only) ----------------------
__device__ __nv_bfloat16 g_Xhi[R_TOT * D_DIM];          // X hi, row-major
__device__ __nv_bfloat16 g_Xlo[R_TOT * D_DIM];          // X lo
__device__ __nv_bfloat16 g_B1hi[13 * 128 * 128];        // W1^T [net][n][k]
__device__ __nv_bfloat16 g_B1lo[13 * 128 * 128];
__device__ __nv_bfloat16 g_B2ghi[128 * 128];            // gW2^T [n][k]
__device__ __nv_bfloat16 g_B2glo[128 * 128];
__device__ __nv_bfloat16 g_B2fhi[12 * 16 * 128];        // fW2^T padded N=16
__device__ float g_Vres[R_TOT * D_DIM];                 // fp32 residual (exact)
__device__ __nv_bfloat16 g_VresBf[R_TOT * D_DIM];       // bf16 residual mirror
__device__ __nv_bfloat16 g_Vbf0[R_TOT * D_DIM];         // bf16 V ping
__device__ __nv_bfloat16 g_Vbf1[R_TOT * D_DIM];         // bf16 V pong
__device__ float g_Wall[M_NET * R_TOT * K_LNK];

// ---------------- helpers ---------------------------------------------------
__device__ __forceinline__ u32 smem_u32(const void* p) {
    u32 a;
    asm("{ .reg .u64 t; cvta.to.shared.u64 t, %1; cvt.u32.u64 %0, t; }"
        : "=r"(a) : "l"(p));
    return a;
}
__device__ __forceinline__ void ldsm4(u32* r, u32 addr) {
    asm volatile("ldmatrix.sync.aligned.m8n8.x4.shared.b16 {%0,%1,%2,%3}, [%4];"
        : "=r"(r[0]), "=r"(r[1]), "=r"(r[2]), "=r"(r[3]) : "r"(addr));
}
__device__ __forceinline__ void mma16816(float* d, const u32* a, const u32* b) {
    asm volatile(
        "mma.sync.aligned.m16n8k16.row.col.f32.bf16.bf16.f32 "
        "{%0,%1,%2,%3}, {%4,%5,%6,%7}, {%8,%9}, {%0,%1,%2,%3};"
        : "+f"(d[0]), "+f"(d[1]), "+f"(d[2]), "+f"(d[3])
        : "r"(a[0]), "r"(a[1]), "r"(a[2]), "r"(a[3]), "r"(b[0]), "r"(b[1]));
}
// swizzled byte address of 16B unit (r, c16) in a [rows][128]bf16 smem tile
__device__ __forceinline__ u32 sw_addr(u32 base, int r, int c16) {
    return base + (u32)(((r << 4) + (c16 ^ (r & 7))) << 4);
}
__device__ __forceinline__ void bf_split(float v, unsigned short& h,
                                         unsigned short& l) {
    __nv_bfloat16 hb = __float2bfloat16(v);
    __nv_bfloat16 lb = __float2bfloat16(v - __bfloat162float(hb));
    h = __bfloat16_as_ushort(hb);
    l = __bfloat16_as_ushort(lb);
}
// pack two fp32 -> bf16x2 (lo arg in low half = memory-first element)
__device__ __forceinline__ u32 pack_bf16x2(float lo, float hi) {
    u32 r;
    asm("cvt.rn.bf16x2.f32 %0, %1, %2;" : "=r"(r) : "f"(hi), "f"(lo));
    return r;
}
__device__ __forceinline__ void fma_bf2(u32& d, u32 a, u32 b) {
    asm("fma.rn.bf16x2 %0, %1, %2, %0;" : "+r"(d) : "r"(a), "r"(b));
}
__device__ __forceinline__ u32 add_bf2(u32 a, u32 b) {
    u32 r;
    asm("add.rn.bf16x2 %0, %1, %2;" : "=r"(r) : "r"(a), "r"(b));
    return r;
}
__device__ __forceinline__ float gelu_exact(float x) {
    return 0.5f * x * (1.0f + erff(x * 0.70710678118654752440f));
}

// ---------------------------------------------------------------------------
// Prep: transpose + bf16-split weights into [n][k] row-major hi/lo.
// ---------------------------------------------------------------------------
#define PREP_A (13 * 128 * 64)
#define PREP_B (128 * 64)
#define PREP_C (12 * 16 * 64)
#define PREP_TOT (PREP_A + PREP_B + PREP_C)

__global__ void k_prep(const float* __restrict__ gW1,
                       const float* __restrict__ gW2,
                       const float* __restrict__ fW1,
                       const float* __restrict__ fW2) {
    int t = blockIdx.x * blockDim.x + threadIdx.x;
    if (t >= PREP_TOT) return;

    float w0, w1;
    if (t < PREP_A) {
        int net = t >> 13;
        int r = t & 8191;
        int n = r >> 6, k = (r & 63) * 2;
        const float* W1 = (net == 0) ? gW1 : fW1 + (size_t)(net - 1) * 128 * 128;
        w0 = W1[k * 128 + n];
        w1 = W1[(k + 1) * 128 + n];
        int widx = (net * 128 + n) * 64 + (k >> 1);
        unsigned short h0, l0, h1, l1;
        bf_split(w0, h0, l0); bf_split(w1, h1, l1);
        ((u32*)g_B1hi)[widx] = (u32)h0 | ((u32)h1 << 16);
        ((u32*)g_B1lo)[widx] = (u32)l0 | ((u32)l1 << 16);
    } else if (t < PREP_A + PREP_B) {
        int r = t - PREP_A;
        int n = r >> 6, k = (r & 63) * 2;
        w0 = gW2[k * 128 + n];
        w1 = gW2[(k + 1) * 128 + n];
        int widx = n * 64 + (k >> 1);
        unsigned short h0, l0, h1, l1;
        bf_split(w0, h0, l0); bf_split(w1, h1, l1);
        ((u32*)g_B2ghi)[widx] = (u32)h0 | ((u32)h1 << 16);
        ((u32*)g_B2glo)[widx] = (u32)l0 | ((u32)l1 << 16);
    } else {
        int r = t - PREP_A - PREP_B;
        int net = r >> 10;
        int rr = r & 1023;
        int n = rr >> 6, k = (rr & 63) * 2;
        w0 = (n < 13) ? fW2[(size_t)net * 128 * 13 + k * 13 + n] : 0.0f;
        w1 = (n < 13) ? fW2[(size_t)net * 128 * 13 + (k + 1) * 13 + n] : 0.0f;
        ((u32*)g_B2fhi)[(net * 16 + n) * 64 + (k >> 1)] =
            pack_bf16x2(w0, w1);
    }
}

// ---------------------------------------------------------------------------
// Embed: x = emb[data] + apc -> bf16 hi/lo row-major.
// ---------------------------------------------------------------------------
__global__ void k_embed(const int* __restrict__ data,
                        const float* __restrict__ emb,
                        const float* __restrict__ apc) {
    int idx = blockIdx.x * blockDim.x + threadIdx.x;   // R_TOT*16 threads
    int row = idx >> 4;
    int g8 = idx & 15;
    int tok = data[row];
    int s = row & (S_LEN - 1);
    float4 e0 = ((const float4*)emb)[tok * 32 + g8 * 2];
    float4 e1 = ((const float4*)emb)[tok * 32 + g8 * 2 + 1];
    float4 a0 = ((const float4*)apc)[s * 32 + g8 * 2];
    float4 a1 = ((const float4*)apc)[s * 32 + g8 * 2 + 1];
    float v[8] = {e0.x + a0.x, e0.y + a0.y, e0.z + a0.z, e0.w + a0.w,
                  e1.x + a1.x, e1.y + a1.y, e1.z + a1.z, e1.w + a1.w};
    u32 hp[4], lp[4];
    #pragma unroll
    for (int p = 0; p < 4; ++p) {
        unsigned short h0, l0, h1, l1;
        bf_split(v[2 * p], h0, l0);
        bf_split(v[2 * p + 1], h1, l1);
        hp[p] = (u32)h0 | ((u32)h1 << 16);
        lp[p] = (u32)l0 | ((u32)l1 << 16);
    }
    ((uint4*)g_Xhi)[row * 16 + g8] = make_uint4(hp[0], hp[1], hp[2], hp[3]);
    ((uint4*)g_Xlo)[row * 16 + g8] = make_uint4(lp[0], lp[1], lp[2], lp[3]);
}

// ---------------------------------------------------------------------------
// k_mlp: warp-MMA fused 2-layer MLP.
// m==0 (g-net): 3-term bf16 hi/lo split (feeds the fp32 backbone).
// m>=1 (f-nets): single-term plain bf16.
// grid = (128 row-tiles, 13 nets), 512 threads (16 warps, warp tile 32x32).
// ---------------------------------------------------------------------------
#define SM_W1HI  0
#define SM_W1LO  32768
#define SM_XHHI  65536
#define SM_XHLO  98304
#define SM_F2HI  131072
#define SM_B1S   139264
#define SM_B2S   139776
#define SMEM_MLP 140288

extern __shared__ char smc[];

__global__ void __launch_bounds__(512, 1) k_mlp(
    const float* __restrict__ gb1, const float* __restrict__ gb2,
    const float* __restrict__ fb1, const float* __restrict__ fb2) {
    const int tid = threadIdx.x;
    const int lane = tid & 31;
    const int wid = tid >> 5;
    const int m = blockIdx.y;
    const int row0 = blockIdx.x * 128;
    const u32 sbase = smem_u32(smc);
    float* b1s = (float*)(smc + SM_B1S);
    float* b2s = (float*)(smc + SM_B2S);

    // ---- stage into swizzled smem (lo regions only for g-net) ----
    {
        const uint4* s1h = (const uint4*)g_B1hi + m * 2048;
        const uint4* s1l = (const uint4*)g_B1lo + m * 2048;
        const uint4* sxh = (const uint4*)g_Xhi + row0 * 16;
        const uint4* sxl = (const uint4*)g_Xlo + row0 * 16;
        #pragma unroll
        for (int p = 0; p < 4; ++p) {
            int q = tid + p * 512;
            int r = q >> 4, c16 = q & 15;
            u32 d = (u32)(((r << 4) + (c16 ^ (r & 7))) << 4);
            *(uint4*)(smc + SM_W1HI + d) = s1h[q];
            *(uint4*)(smc + SM_XHHI + d) = sxh[q];
            if (m == 0) {
                *(uint4*)(smc + SM_W1LO + d) = s1l[q];
                *(uint4*)(smc + SM_XHLO + d) = sxl[q];
            }
        }
    }
    if (m > 0) {
        const uint4* sfh = (const uint4*)g_B2fhi + (m - 1) * 256;
        if (tid < 256) {
            int r = tid >> 4, c16 = tid & 15;
            u32 d = (u32)(((r << 4) + (c16 ^ (r & 7))) << 4);
            *(uint4*)(smc + SM_F2HI + d) = sfh[tid];
        }
        if (tid < 128) b1s[tid] = fb1[(m - 1) * 128 + tid];
        if (tid < 16)  b2s[tid] = (tid < 13) ? fb2[(m - 1) * 13 + tid] : 0.0f;
    } else {
        if (tid < 128) { b1s[tid] = gb1[tid]; b2s[tid] = gb2[tid]; }
    }
    __syncthreads();

    // fragment lane offsets
    const int a_ro = (lane & 7) + (lane & 8);
    const int a_co = lane >> 4;
    const int b_ro = (lane & 7) + ((lane >> 1) & 8);
    const int b_co = (lane >> 3) & 1;
    const int tq = lane >> 2;
    const int tr = (lane & 3) * 2;

    const int wm = (wid & 3) * 32;    // warp M offset
    const int wn = (wid >> 2) * 32;   // warp N offset

    // ================= Layer 1: H = gelu(X @ W1 + b1) ======================
    float acc[2][4][4];
    #pragma unroll
    for (int i = 0; i < 2; ++i)
        #pragma unroll
        for (int j = 0; j < 4; ++j)
            #pragma unroll
            for (int q = 0; q < 4; ++q) acc[i][j][q] = 0.0f;

    if (m == 0) {
        #pragma unroll
        for (int k = 0; k < 8; ++k) {
            const int kc = k * 2;
            u32 ah[2][4], al[2][4], bh[2][4], bl[2][4];
            #pragma unroll
            for (int mt = 0; mt < 2; ++mt) {
                int r = wm + mt * 16 + a_ro;
                ldsm4(ah[mt], sw_addr(sbase + SM_XHHI, r, kc + a_co));
                ldsm4(al[mt], sw_addr(sbase + SM_XHLO, r, kc + a_co));
            }
            #pragma unroll
            for (int ng = 0; ng < 2; ++ng) {
                int r = wn + ng * 16 + b_ro;
                ldsm4(bh[ng], sw_addr(sbase + SM_W1HI, r, kc + b_co));
                ldsm4(bl[ng], sw_addr(sbase + SM_W1LO, r, kc + b_co));
            }
            #pragma unroll
            for (int mt = 0; mt < 2; ++mt)
                #pragma unroll
                for (int ng = 0; ng < 2; ++ng) {
                    mma16816(acc[mt][2 * ng],     ah[mt], &bh[ng][0]);
                    mma16816(acc[mt][2 * ng + 1], ah[mt], &bh[ng][2]);
                    mma16816(acc[mt][2 * ng],     ah[mt], &bl[ng][0]);
                    mma16816(acc[mt][2 * ng + 1], ah[mt], &bl[ng][2]);
                    mma16816(acc[mt][2 * ng],     al[mt], &bh[ng][0]);
                    mma16816(acc[mt][2 * ng + 1], al[mt], &bh[ng][2]);
                }
        }
    } else {
        #pragma unroll
        for (int k = 0; k < 8; ++k) {
            const int kc = k * 2;
            u32 ah[2][4], bh[2][4];
            #pragma unroll
            for (int mt = 0; mt < 2; ++mt)
                ldsm4(ah[mt], sw_addr(sbase + SM_XHHI, wm + mt * 16 + a_ro, kc + a_co));
            #pragma unroll
            for (int ng = 0; ng < 2; ++ng)
                ldsm4(bh[ng], sw_addr(sbase + SM_W1HI, wn + ng * 16 + b_ro, kc + b_co));
            #pragma unroll
            for (int mt = 0; mt < 2; ++mt)
                #pragma unroll
                for (int ng = 0; ng < 2; ++ng) {
                    mma16816(acc[mt][2 * ng],     ah[mt], &bh[ng][0]);
                    mma16816(acc[mt][2 * ng + 1], ah[mt], &bh[ng][2]);
                }
        }
    }
    __syncthreads();   // everyone done reading X before H overwrites it

    // epilogue 1: bias + gelu (+ split for g-net), H -> XH region
    #pragma unroll
    for (int mt = 0; mt < 2; ++mt)
        #pragma unroll
        for (int nt = 0; nt < 4; ++nt) {
            int r = wm + mt * 16 + tq;
            int c = wn + nt * 8 + tr;
            float v0 = gelu_exact(acc[mt][nt][0] + b1s[c]);
            float v1 = gelu_exact(acc[mt][nt][1] + b1s[c + 1]);
            float v2 = gelu_exact(acc[mt][nt][2] + b1s[c]);
            float v3 = gelu_exact(acc[mt][nt][3] + b1s[c + 1]);
            int c16 = c >> 3, cb = (c & 7) * 2;
            u32 d0 = sw_addr(sbase + SM_XHHI, r, c16) - sbase + cb;
            u32 d8 = sw_addr(sbase + SM_XHHI, r + 8, c16) - sbase + cb;
            if (m == 0) {
                unsigned short h0, l0, h1, l1, h2, l2, h3, l3;
                bf_split(v0, h0, l0); bf_split(v1, h1, l1);
                bf_split(v2, h2, l2); bf_split(v3, h3, l3);
                *(u32*)(smc + d0) = (u32)h0 | ((u32)h1 << 16);
                *(u32*)(smc + d8) = (u32)h2 | ((u32)h3 << 16);
                *(u32*)(smc + d0 + (SM_XHLO - SM_XHHI)) = (u32)l0 | ((u32)l1 << 16);
                *(u32*)(smc + d8 + (SM_XHLO - SM_XHHI)) = (u32)l2 | ((u32)l3 << 16);
            } else {
                *(u32*)(smc + d0) = pack_bf16x2(v0, v1);
                *(u32*)(smc + d8) = pack_bf16x2(v2, v3);
            }
        }

    // m==0: restage gW2^T over the consumed W1 region
    if (m == 0) {
        const uint4* s2h = (const uint4*)g_B2ghi;
        const uint4* s2l = (const uint4*)g_B2glo;
        #pragma unroll
        for (int p = 0; p < 4; ++p) {
            int q = tid + p * 512;
            int r = q >> 4, c16 = q & 15;
            u32 d = (u32)(((r << 4) + (c16 ^ (r & 7))) << 4);
            *(uint4*)(smc + SM_W1HI + d) = s2h[q];
            *(uint4*)(smc + SM_W1LO + d) = s2l[q];
        }
    }
    __syncthreads();

    // ================= Layer 2 =============================================
    if (m == 0) {
        float ac2[2][4][4];
        #pragma unroll
        for (int i = 0; i < 2; ++i)
            #pragma unroll
            for (int j = 0; j < 4; ++j)
                #pragma unroll
                for (int q = 0; q < 4; ++q) ac2[i][j][q] = 0.0f;
        #pragma unroll
        for (int k = 0; k < 8; ++k) {
            const int kc = k * 2;
            u32 ah[2][4], al[2][4], bh[2][4], bl[2][4];
            #pragma unroll
            for (int mt = 0; mt < 2; ++mt) {
                int r = wm + mt * 16 + a_ro;
                ldsm4(ah[mt], sw_addr(sbase + SM_XHHI, r, kc + a_co));
                ldsm4(al[mt], sw_addr(sbase + SM_XHLO, r, kc + a_co));
            }
            #pragma unroll
            for (int ng = 0; ng < 2; ++ng) {
                int r = wn + ng * 16 + b_ro;
                ldsm4(bh[ng], sw_addr(sbase + SM_W1HI, r, kc + b_co));
                ldsm4(bl[ng], sw_addr(sbase + SM_W1LO, r, kc + b_co));
            }
            #pragma unroll
            for (int mt = 0; mt < 2; ++mt)
                #pragma unroll
                for (int ng = 0; ng < 2; ++ng) {
                    mma16816(ac2[mt][2 * ng],     ah[mt], &bh[ng][0]);
                    mma16816(ac2[mt][2 * ng + 1], ah[mt], &bh[ng][2]);
                    mma16816(ac2[mt][2 * ng],     ah[mt], &bl[ng][0]);
                    mma16816(ac2[mt][2 * ng + 1], ah[mt], &bl[ng][2]);
                    mma16816(ac2[mt][2 * ng],     al[mt], &bh[ng][0]);
                    mma16816(ac2[mt][2 * ng + 1], al[mt], &bh[ng][2]);
                }
        }
        #pragma unroll
        for (int mt = 0; mt < 2; ++mt)
            #pragma unroll
            for (int nt = 0; nt < 4; ++nt) {
                int r = wm + mt * 16 + tq;
                int c = wn + nt * 8 + tr;
                float2 o0 = make_float2(ac2[mt][nt][0] + b2s[c],
                                        ac2[mt][nt][1] + b2s[c + 1]);
                float2 o1 = make_float2(ac2[mt][nt][2] + b2s[c],
                                        ac2[mt][nt][3] + b2s[c + 1]);
                *(float2*)(g_Vres + (size_t)(row0 + r) * 128 + c) = o0;
                *(float2*)(g_Vres + (size_t)(row0 + r + 8) * 128 + c) = o1;
                // bf16 residual mirror (= scan step-0 input AND intermediate res)
                *(u32*)((__nv_bfloat16*)g_VresBf + (size_t)(row0 + r) * 128 + c) =
                    pack_bf16x2(o0.x, o0.y);
                *(u32*)((__nv_bfloat16*)g_VresBf + (size_t)(row0 + r + 8) * 128 + c) =
                    pack_bf16x2(o1.x, o1.y);
            }
    } else if (wid < 8) {
        const int wm2 = wid * 16;
        float ac2[2][4];
        #pragma unroll
        for (int j = 0; j < 2; ++j)
            #pragma unroll
            for (int q = 0; q < 4; ++q) ac2[j][q] = 0.0f;
        #pragma unroll
        for (int k = 0; k < 8; ++k) {
            const int kc = k * 2;
            u32 ah[4], bh[4];
            ldsm4(ah, sw_addr(sbase + SM_XHHI, wm2 + a_ro, kc + a_co));
            ldsm4(bh, sw_addr(sbase + SM_F2HI, b_ro, kc + b_co));
            mma16816(ac2[0], ah, &bh[0]);
            mma16816(ac2[1], ah, &bh[2]);
        }
        float* op = g_Wall + (size_t)(m - 1) * R_TOT * K_LNK
                           + (size_t)row0 * K_LNK;
        #pragma unroll
        for (int nt = 0; nt < 2; ++nt) {
            int c = nt * 8 + tr;
            int r = wm2 + tq;
            if (c < 13) {
                op[(r) * K_LNK + c]     = ac2[nt][0] + b2s[c];
                op[(r + 8) * K_LNK + c] = ac2[nt][2] + b2s[c];
            }
            if (c + 1 < 13) {
                op[(r) * K_LNK + c + 1]     = ac2[nt][1] + b2s[c + 1];
                op[(r + 8) * K_LNK + c + 1] = ac2[nt][3] + b2s[c + 1];
            }
        }
    }
}

// ---------------------------------------------------------------------------
// k_scan: chord-mix step, TWO rows per warp.
// Lanes 0-15 hold row A (8 bf16 each via uint4), lanes 16-31 row B.
// One indexed shfl (k | (lane&16)) broadcasts the row-appropriate (w, idx).
// Mix accumulated in bf16x2; residual: bf16 (intermediate) / fp32 (final).
// ---------------------------------------------------------------------------
__global__ void __launch_bounds__(256) k_scan(int m, const int* __restrict__ cols,
                                              float* __restrict__ out_final) {
    const __nv_bfloat16* Vin = (m == 0) ? g_VresBf
                                        : ((m & 1) ? g_Vbf1 : g_Vbf0);
    __nv_bfloat16* Vout = ((m + 1) & 1) ? g_Vbf1 : g_Vbf0;
    const float* Wm = g_Wall + (size_t)m * R_TOT * K_LNK;

    const int lane = threadIdx.x & 31;
    const int pair = (blockIdx.x * blockDim.x + threadIdx.x) >> 5;
    const int hl   = lane & 15;
    const int lr   = pair * 2 + (lane >> 4);    // this half-warp's row

    u32 wv = 0; int iv = 0;
    if (hl < K_LNK) {
        float w = Wm[lr * K_LNK + hl];
        wv = pack_bf16x2(w, w);
        int s = lr & (S_LEN - 1), b = lr >> 12;
        iv = ((b << 12) | cols[s * K_LNK + hl]) << 4;   // uint4 row base (16/row)
    }

    const uint4* Vin4 = (const uint4*)Vin;
    u32 a0 = 0, a1 = 0, a2 = 0, a3 = 0;        // bf16x2 mix accumulators
    const int selk = lane & 16;
    #pragma unroll
    for (int k = 0; k < K_LNK; ++k) {
        u32 wk = __shfl_sync(0xffffffffu, wv, k | selk);
        int ik = __shfl_sync(0xffffffffu, iv, k | selk);
        uint4 v = Vin4[ik + hl];
        fma_bf2(a0, v.x, wk);
        fma_bf2(a1, v.y, wk);
        fma_bf2(a2, v.z, wk);
        fma_bf2(a3, v.w, wk);
    }

    if (m == M_NET - 1) {
        // exact fp32 residual for the final output
        const float4* res4 = (const float4*)g_Vres + ((size_t)lr << 5);
        float4 r0 = res4[hl * 2], r1 = res4[hl * 2 + 1];
        r0.x += __uint_as_float(a0 << 16);
        r0.y += __uint_as_float(a0 & 0xFFFF0000u);
        r0.z += __uint_as_float(a1 << 16);
        r0.w += __uint_as_float(a1 & 0xFFFF0000u);
        r1.x += __uint_as_float(a2 << 16);
        r1.y += __uint_as_float(a2 & 0xFFFF0000u);
        r1.z += __uint_as_float(a3 << 16);
        r1.w += __uint_as_float(a3 & 0xFFFF0000u);
        float4* op = (float4*)out_final + ((size_t)lr << 5);
        op[hl * 2]     = r0;
        op[hl * 2 + 1] = r1;
    } else {
        // bf16 residual: output is bf16-rounded anyway
        uint4 r = ((const uint4*)g_VresBf)[((size_t)lr << 4) + hl];
        uint4 o;
        o.x = add_bf2(r.x, a0);
        o.y = add_bf2(r.y, a1);
        o.z = add_bf2(r.z, a2);
        o.w = add_bf2(r.w, a3);
        ((uint4*)Vout)[((size_t)lr << 4) + hl] = o;
    }
}

// ---------------------------------------------------------------------------
extern "C" void kernel_launch(void* const* d_in, const int* in_sizes, int n_in,
                              void* d_out, int out_size) {
    const int*   data = (const int*)  d_in[0];
    const int*   cols = (const int*)  d_in[1];
    const float* emb  = (const float*)d_in[2];
    const float* apc  = (const float*)d_in[3];
    const float* gW1  = (const float*)d_in[4];
    const float* gb1  = (const float*)d_in[5];
    const float* gW2  = (const float*)d_in[6];
    const float* gb2  = (const float*)d_in[7];
    const float* fW1  = (const float*)d_in[8];
    const float* fb1  = (const float*)d_in[9];
    const float* fW2  = (const float*)d_in[10];
    const float* fb2  = (const float*)d_in[11];
    float* out = (float*)d_out;

    cudaFuncSetAttribute(k_mlp, cudaFuncAttributeMaxDynamicSharedMemorySize,
                         SMEM_MLP);

    // 1) weight prep (transpose + bf16 split)
    k_prep<<<(PREP_TOT + 255) / 256, 256>>>(gW1, gW2, fW1, fW2);

    // 2) embeddings -> bf16 hi/lo
    k_embed<<<(R_TOT * 16) / 256, 256>>>(data, emb, apc);

    // 3) all 13 fused MLPs on warp tensor cores
    dim3 grid_mlp(R_TOT / 128, 13);
    k_mlp<<<grid_mlp, 512, SMEM_MLP>>>(gb1, gb2, fb1, fb2);

    // 4) 12 chord-mix scan steps (2 rows/warp, bf16 gathers + bf16 res)
    for (int m = 0; m < M_NET; ++m)
        k_scan<<<R_TOT / 16, 256>>>(m, cols, out);
}